// round 6
// baseline (speedup 1.0000x reference)
#include <cuda_runtime.h>
#include <cuda_bf16.h>
#include <math.h>
#include <stdint.h>

#define B_ 4
#define S_ 2048
#define E_ 1024
#define H_ 16
#define D_ 64

static const int MTOT = B_ * S_;          // 8192
#define NELEM (B_ * S_ * E_)              // 8388608

// ---------------- scratch (__device__ globals; no allocs allowed) ----------
__device__ float g_Q[NELEM];
__device__ float g_K[NELEM];
__device__ __nv_bfloat16 g_Ahi[NELEM];
__device__ __nv_bfloat16 g_Alo[NELEM];
__device__ __nv_bfloat16 g_Whi[E_ * E_];
__device__ __nv_bfloat16 g_Wlo[E_ * E_];
__device__ __nv_bfloat16 g_Qhi[NELEM];
__device__ __nv_bfloat16 g_Qlo[NELEM];
__device__ __nv_bfloat16 g_Khi[NELEM];
__device__ __nv_bfloat16 g_Klo[NELEM];
__device__ __nv_bfloat16 g_Vhi[NELEM];
__device__ __nv_bfloat16 g_Vlo[NELEM];

// ---------------- helpers --------------------------------------------------
__device__ __forceinline__ uint32_t smem_u32(const void* p) {
    uint32_t a;
    asm("{ .reg .u64 t; cvta.to.shared.u64 t, %1; cvt.u32.u64 %0, t; }"
        : "=r"(a) : "l"(p));
    return a;
}
__device__ __forceinline__ void cp16(uint32_t saddr, const void* g) {
    asm volatile("cp.async.cg.shared.global [%0], [%1], 16;"
                 :: "r"(saddr), "l"(g) : "memory");
}
__device__ __forceinline__ void ldsm4(uint32_t* r, uint32_t a) {
    asm volatile("ldmatrix.sync.aligned.m8n8.x4.shared.b16 {%0,%1,%2,%3}, [%4];"
                 : "=r"(r[0]), "=r"(r[1]), "=r"(r[2]), "=r"(r[3]) : "r"(a));
}
__device__ __forceinline__ void ldsm4t(uint32_t* r, uint32_t a) {
    asm volatile("ldmatrix.sync.aligned.m8n8.x4.trans.shared.b16 {%0,%1,%2,%3}, [%4];"
                 : "=r"(r[0]), "=r"(r[1]), "=r"(r[2]), "=r"(r[3]) : "r"(a));
}
__device__ __forceinline__ void mma16816(float* c, const uint32_t* a,
                                         const uint32_t* b) {
    asm volatile(
        "mma.sync.aligned.m16n8k16.row.col.f32.bf16.bf16.f32 "
        "{%0,%1,%2,%3}, {%4,%5,%6,%7}, {%8,%9}, {%0,%1,%2,%3};"
        : "+f"(c[0]), "+f"(c[1]), "+f"(c[2]), "+f"(c[3])
        : "r"(a[0]), "r"(a[1]), "r"(a[2]), "r"(a[3]), "r"(b[0]), "r"(b[1]));
}
__device__ __forceinline__ void split2(float x0, float x1, uint32_t& hi,
                                       uint32_t& lo) {
    __nv_bfloat16 h0 = __float2bfloat16(x0);
    __nv_bfloat16 h1 = __float2bfloat16(x1);
    __nv_bfloat16 l0 = __float2bfloat16(x0 - __bfloat162float(h0));
    __nv_bfloat16 l1 = __float2bfloat16(x1 - __bfloat162float(h1));
    hi = (uint32_t)*(uint16_t*)&h0 | ((uint32_t)*(uint16_t*)&h1 << 16);
    lo = (uint32_t)*(uint16_t*)&l0 | ((uint32_t)*(uint16_t*)&l1 << 16);
}

// ---------------- split fp32 -> bf16 hi/lo --------------------------------
__global__ __launch_bounds__(256)
void split_bf16(const float* __restrict__ src, __nv_bfloat16* __restrict__ hi,
                __nv_bfloat16* __restrict__ lo, int n4) {
    int i = blockIdx.x * blockDim.x + threadIdx.x;
    if (i >= n4) return;
    float4 v = ((const float4*)src)[i];
    float f[4] = {v.x, v.y, v.z, v.w};
    __nv_bfloat16 h[4], l[4];
#pragma unroll
    for (int j = 0; j < 4; j++) {
        h[j] = __float2bfloat16(f[j]);
        l[j] = __float2bfloat16(f[j] - __bfloat162float(h[j]));
    }
    ((uint2*)hi)[i] = *(uint2*)h;
    ((uint2*)lo)[i] = *(uint2*)l;
}

// ---------------- mma.sync GEMM ---------------------------------------------
// 128x128 CTA tile, BK=32, 8 warps (2x4), 4-stage cp.async ring,
// term-major MMA ordering (acc reuse distance 16).
#define TILEB 10240
#define STAGEB 40960
#define GEMM_SMEM (4 * STAGEB)

__device__ __forceinline__ void load_stage(
    uint32_t sb, int st, const __nv_bfloat16* __restrict__ Ahi,
    const __nv_bfloat16* __restrict__ Alo, const __nv_bfloat16* __restrict__ Bhi,
    const __nv_bfloat16* __restrict__ Blo, int bm, int bn, int k0, int tid) {
    uint32_t s0 = sb + st * STAGEB;
#pragma unroll
    for (int p = 0; p < 2; p++) {
        int chunk = tid + p * 256;
        int row = chunk >> 2;
        int kc = chunk & 3;
        uint32_t soff = (uint32_t)(row * 80 + kc * 16);
        size_t ga = ((size_t)(bm + row) << 10) + k0 + kc * 8;
        size_t gb = ((size_t)(bn + row) << 10) + k0 + kc * 8;
        cp16(s0 + soff,             Ahi + ga);
        cp16(s0 + TILEB + soff,     Alo + ga);
        cp16(s0 + 2 * TILEB + soff, Bhi + gb);
        cp16(s0 + 3 * TILEB + soff, Blo + gb);
    }
}

__global__ __launch_bounds__(256)
void gemm_mma(const __nv_bfloat16* __restrict__ Ahi,
              const __nv_bfloat16* __restrict__ Alo,
              const __nv_bfloat16* __restrict__ Whi,
              const __nv_bfloat16* __restrict__ Wlo,
              float* __restrict__ C,
              __nv_bfloat16* __restrict__ Chi,
              __nv_bfloat16* __restrict__ Clo) {
    extern __shared__ char smem[];
    const uint32_t sb = smem_u32(smem);
    const int tid = threadIdx.x;
    const int lane = tid & 31;
    const int wid = tid >> 5;
    const int wm = wid >> 2;
    const int wn = wid & 3;
    const int bm = blockIdx.y * 128;
    const int bn = blockIdx.x * 128;

    float acc[4][4][4];
#pragma unroll
    for (int i = 0; i < 4; i++)
#pragma unroll
        for (int j = 0; j < 4; j++)
#pragma unroll
            for (int r = 0; r < 4; r++) acc[i][j][r] = 0.f;

    const int NCH = E_ / 32;   // 32
    // prologue: fill 3 stages
#pragma unroll
    for (int p = 0; p < 3; p++) {
        load_stage(sb, p, Ahi, Alo, Whi, Wlo, bm, bn, p * 32, tid);
        asm volatile("cp.async.commit_group;" ::: "memory");
    }

    for (int c = 0; c < NCH; c++) {
        if (c + 2 < NCH)
            asm volatile("cp.async.wait_group 2;" ::: "memory");
        else if (c + 1 < NCH)
            asm volatile("cp.async.wait_group 1;" ::: "memory");
        else
            asm volatile("cp.async.wait_group 0;" ::: "memory");
        __syncthreads();
        if (c + 3 < NCH) {
            load_stage(sb, (c + 3) & 3, Ahi, Alo, Whi, Wlo, bm, bn,
                       (c + 3) * 32, tid);
            asm volatile("cp.async.commit_group;" ::: "memory");
        }

        const uint32_t s0 = sb + (c & 3) * STAGEB;
        const uint32_t sAh = s0, sAl = s0 + TILEB;
        const uint32_t sBh = s0 + 2 * TILEB, sBl = s0 + 3 * TILEB;

#pragma unroll
        for (int ks = 0; ks < 32; ks += 16) {
            uint32_t ahi[4][4], alo[4][4], bhi[2][4], blo[2][4];
            const int arow = wm * 64 + (lane & 7) + ((lane >> 3) & 1) * 8;
            const int akk = ks + (lane >> 4) * 8;
#pragma unroll
            for (int mi = 0; mi < 4; mi++) {
                uint32_t ao = (uint32_t)((arow + mi * 16) * 80 + akk * 2);
                ldsm4(ahi[mi], sAh + ao);
                ldsm4(alo[mi], sAl + ao);
            }
            const int brow = wn * 32 + (lane & 7) + ((lane >> 4) & 1) * 8;
            const int bkk = ks + ((lane >> 3) & 1) * 8;
#pragma unroll
            for (int nb = 0; nb < 2; nb++) {
                uint32_t bo = (uint32_t)((brow + nb * 16) * 80 + bkk * 2);
                ldsm4(bhi[nb], sBh + bo);
                ldsm4(blo[nb], sBl + bo);
            }
            // term-major: 16 independent MMAs per pass
#pragma unroll
            for (int mi = 0; mi < 4; mi++)
#pragma unroll
                for (int ni = 0; ni < 4; ni++)
                    mma16816(acc[mi][ni], ahi[mi], &bhi[ni >> 1][(ni & 1) * 2]);
#pragma unroll
            for (int mi = 0; mi < 4; mi++)
#pragma unroll
                for (int ni = 0; ni < 4; ni++)
                    mma16816(acc[mi][ni], ahi[mi], &blo[ni >> 1][(ni & 1) * 2]);
#pragma unroll
            for (int mi = 0; mi < 4; mi++)
#pragma unroll
                for (int ni = 0; ni < 4; ni++)
                    mma16816(acc[mi][ni], alo[mi], &bhi[ni >> 1][(ni & 1) * 2]);
        }
    }

    const int r0 = bm + wm * 64 + (lane >> 2);
    const int c0 = bn + wn * 32 + (lane & 3) * 2;
    if (C) {
#pragma unroll
        for (int mi = 0; mi < 4; mi++)
#pragma unroll
            for (int ni = 0; ni < 4; ni++) {
                int row = r0 + mi * 16;
                int col = c0 + ni * 8;
                *(float2*)&C[(size_t)row * E_ + col] =
                    make_float2(acc[mi][ni][0], acc[mi][ni][1]);
                *(float2*)&C[(size_t)(row + 8) * E_ + col] =
                    make_float2(acc[mi][ni][2], acc[mi][ni][3]);
            }
    }
    if (Chi) {
#pragma unroll
        for (int mi = 0; mi < 4; mi++)
#pragma unroll
            for (int ni = 0; ni < 4; ni++) {
                int row = r0 + mi * 16;
                int col = c0 + ni * 8;
                uint32_t h0, l0v, h1, l1v;
                split2(acc[mi][ni][0], acc[mi][ni][1], h0, l0v);
                split2(acc[mi][ni][2], acc[mi][ni][3], h1, l1v);
                *(uint32_t*)&Chi[(size_t)row * E_ + col] = h0;
                *(uint32_t*)&Clo[(size_t)row * E_ + col] = l0v;
                *(uint32_t*)&Chi[(size_t)(row + 8) * E_ + col] = h1;
                *(uint32_t*)&Clo[(size_t)(row + 8) * E_ + col] = l1v;
            }
    }
}

// ---------------- RoPE + bf16 split. Q gets 1/8 scale folded in. ----------
__global__ void rope_split(const float* __restrict__ Q, const float* __restrict__ K,
                           __nv_bfloat16* __restrict__ Qhi, __nv_bfloat16* __restrict__ Qlo,
                           __nv_bfloat16* __restrict__ Khi, __nv_bfloat16* __restrict__ Klo) {
    const int per = B_ * S_ * H_ * 32;
    int idx = blockIdx.x * blockDim.x + threadIdx.x;
    if (idx >= 2 * per) return;
    bool isQ = idx < per;
    int r = isQ ? idx : idx - per;
    int i = r & 31;
    int hh = (r >> 5) & (H_ - 1);
    int s = (r >> 9) & (S_ - 1);
    int b = r >> 20;

    float inv_freq = __expf(-(float)i * (logf(10000.0f) / 32.0f));
    float ang = (float)s * inv_freq;
    float sn, cs;
    sincosf(ang, &sn, &cs);

    size_t base = ((size_t)(b * S_ + s)) * E_ + hh * D_ + i;
    const float* src = isQ ? Q : K;
    float x1 = src[base];
    float x2 = src[base + 32];
    float y1 = x1 * cs - x2 * sn;
    float y2 = x2 * cs + x1 * sn;
    if (isQ) { y1 *= 0.125f; y2 *= 0.125f; }

    __nv_bfloat16* hi = isQ ? Qhi : Khi;
    __nv_bfloat16* lo = isQ ? Qlo : Klo;
    __nv_bfloat16 h1 = __float2bfloat16(y1);
    __nv_bfloat16 h2 = __float2bfloat16(y2);
    hi[base] = h1;
    hi[base + 32] = h2;
    lo[base] = __float2bfloat16(y1 - __bfloat162float(h1));
    lo[base + 32] = __float2bfloat16(y2 - __bfloat162float(h2));
}

// ---------------- tensor-core causal flash attention ----------------------
#define ASTRIDE 72
#define KTILE (64 * ASTRIDE)
#define ASTAGE (4 * KTILE)
#define ATTN_SMEM (2 * ASTAGE * 2)

__device__ __forceinline__ void load_kv(
    uint32_t sb, const __nv_bfloat16* __restrict__ Khi,
    const __nv_bfloat16* __restrict__ Klo, const __nv_bfloat16* __restrict__ Vhi,
    const __nv_bfloat16* __restrict__ Vlo, size_t rowbase, size_t headoff,
    int k0, int tid) {
#pragma unroll
    for (int p = 0; p < 2; p++) {
        int chunk = tid + p * 256;
        int row = chunk >> 3;
        int c8 = chunk & 7;
        size_t g = (rowbase + k0 + row) * E_ + headoff + c8 * 8;
        uint32_t so = (uint32_t)(row * ASTRIDE + c8 * 8) * 2;
        cp16(sb + so,                 Khi + g);
        cp16(sb + KTILE * 2 + so,     Klo + g);
        cp16(sb + 2 * KTILE * 2 + so, Vhi + g);
        cp16(sb + 3 * KTILE * 2 + so, Vlo + g);
    }
}

__global__ __launch_bounds__(256, 2)
void flash_attn_tc(const __nv_bfloat16* __restrict__ Qhi,
                   const __nv_bfloat16* __restrict__ Qlo,
                   const __nv_bfloat16* __restrict__ Khi,
                   const __nv_bfloat16* __restrict__ Klo,
                   const __nv_bfloat16* __restrict__ Vhi,
                   const __nv_bfloat16* __restrict__ Vlo,
                   __nv_bfloat16* __restrict__ Ohi,
                   __nv_bfloat16* __restrict__ Olo) {
    extern __shared__ char smem[];
    const uint32_t sb = smem_u32(smem);
    const int tid = threadIdx.x;
    const int lane = tid & 31;
    const int w = tid >> 5;
    const int qt = gridDim.x - 1 - blockIdx.x;
    const int h = blockIdx.y;
    const int b = blockIdx.z;
    const int q0 = qt * 128;
    const size_t rowbase = (size_t)(b * S_);
    const size_t headoff = (size_t)h * D_;

#pragma unroll
    for (int p = 0; p < 4; p++) {
        int chunk = tid + p * 256;
        int row = chunk >> 3;
        int c8 = chunk & 7;
        size_t g = (rowbase + q0 + row) * E_ + headoff + c8 * 8;
        uint32_t so = (uint32_t)(row * ASTRIDE + c8 * 8) * 2;
        cp16(sb + so, Qhi + g);
        cp16(sb + 2 * KTILE * 2 + so, Qlo + g);
    }
    asm volatile("cp.async.commit_group;" ::: "memory");
    asm volatile("cp.async.wait_group 0;" ::: "memory");
    __syncthreads();

    uint32_t qh[4][4], ql[4][4];
    {
        const int arow = w * 16 + (lane & 7) + ((lane >> 3) & 1) * 8;
#pragma unroll
        for (int ks = 0; ks < 4; ks++) {
            const int koff = ks * 16 + (lane >> 4) * 8;
            uint32_t ao = (uint32_t)(arow * ASTRIDE + koff) * 2;
            ldsm4(qh[ks], sb + ao);
            ldsm4(ql[ks], sb + 2 * KTILE * 2 + ao);
        }
    }
    __syncthreads();

    float m0 = -INFINITY, m1 = -INFINITY, l0 = 0.f, l1 = 0.f;
    float o[8][4];
#pragma unroll
    for (int t = 0; t < 8; t++)
#pragma unroll
        for (int r = 0; r < 4; r++) o[t][r] = 0.f;

    const int nkb = 2 * (qt + 1);
    load_kv(sb, Khi, Klo, Vhi, Vlo, rowbase, headoff, 0, tid);
    asm volatile("cp.async.commit_group;" ::: "memory");

    for (int kt = 0; kt < nkb; kt++) {
        if (kt + 1 < nkb) {
            load_kv(sb + ((kt + 1) & 1) * ASTAGE * 2, Khi, Klo, Vhi, Vlo,
                    rowbase, headoff, (kt + 1) * 64, tid);
            asm volatile("cp.async.commit_group;" ::: "memory");
            asm volatile("cp.async.wait_group 1;" ::: "memory");
        } else {
            asm volatile("cp.async.wait_group 0;" ::: "memory");
        }
        __syncthreads();

        const int k0 = kt * 64;
        const bool skip = (q0 + w * 16 + 15) < k0;
        if (!skip) {
            const uint32_t base = sb + (kt & 1) * ASTAGE * 2;
            float s[8][4];
#pragma unroll
            for (int t = 0; t < 8; t++)
#pragma unroll
                for (int r = 0; r < 4; r++) s[t][r] = 0.f;

            const int nrow = (lane & 7) + ((lane >> 4) & 1) * 8;
#pragma unroll
            for (int ks = 0; ks < 4; ks++) {
                const int koff = ks * 16 + ((lane >> 3) & 1) * 8;
#pragma unroll
                for (int p = 0; p < 4; p++) {
                    uint32_t kh[4], kl[4];
                    uint32_t ao = (uint32_t)((16 * p + nrow) * ASTRIDE + koff) * 2;
                    ldsm4(kh, base + ao);
                    ldsm4(kl, base + KTILE * 2 + ao);
                    mma16816(s[2 * p],     qh[ks], &kh[0]);
                    mma16816(s[2 * p],     qh[ks], &kl[0]);
                    mma16816(s[2 * p],     ql[ks], &kh[0]);
                    mma16816(s[2 * p + 1], qh[ks], &kh[2]);
                    mma16816(s[2 * p + 1], qh[ks], &kl[2]);
                    mma16816(s[2 * p + 1], ql[ks], &kh[2]);
                }
            }

            const int row0 = q0 + w * 16 + (lane >> 2);
            if (kt >= 2 * qt) {
#pragma unroll
                for (int t = 0; t < 8; t++) {
                    int col = k0 + t * 8 + (lane & 3) * 2;
                    if (col > row0)         s[t][0] = -1e30f;
                    if (col + 1 > row0)     s[t][1] = -1e30f;
                    if (col > row0 + 8)     s[t][2] = -1e30f;
                    if (col + 1 > row0 + 8) s[t][3] = -1e30f;
                }
            }

            float mx0 = -INFINITY, mx1 = -INFINITY;
#pragma unroll
            for (int t = 0; t < 8; t++) {
                mx0 = fmaxf(mx0, fmaxf(s[t][0], s[t][1]));
                mx1 = fmaxf(mx1, fmaxf(s[t][2], s[t][3]));
            }
#pragma unroll
            for (int off = 1; off <= 2; off <<= 1) {
                mx0 = fmaxf(mx0, __shfl_xor_sync(0xffffffffu, mx0, off));
                mx1 = fmaxf(mx1, __shfl_xor_sync(0xffffffffu, mx1, off));
            }
            float mn0 = fmaxf(m0, mx0), mn1 = fmaxf(m1, mx1);
            float al0 = __expf(m0 - mn0), al1 = __expf(m1 - mn1);
            m0 = mn0; m1 = mn1;
            float rs0 = 0.f, rs1 = 0.f;
#pragma unroll
            for (int t = 0; t < 8; t++) {
                s[t][0] = __expf(s[t][0] - mn0);
                s[t][1] = __expf(s[t][1] - mn0);
                s[t][2] = __expf(s[t][2] - mn1);
                s[t][3] = __expf(s[t][3] - mn1);
                rs0 += s[t][0] + s[t][1];
                rs1 += s[t][2] + s[t][3];
            }
#pragma unroll
            for (int off = 1; off <= 2; off <<= 1) {
                rs0 += __shfl_xor_sync(0xffffffffu, rs0, off);
                rs1 += __shfl_xor_sync(0xffffffffu, rs1, off);
            }
            l0 = l0 * al0 + rs0;
            l1 = l1 * al1 + rs1;
#pragma unroll
            for (int t = 0; t < 8; t++) {
                o[t][0] *= al0; o[t][1] *= al0;
                o[t][2] *= al1; o[t][3] *= al1;
            }

            const int vrow0 = lane & 15;
            const int vcoff = (lane >> 4) * 8;
#pragma unroll
            for (int j = 0; j < 4; j++) {
                uint32_t ph[4], pl[4];
                split2(s[2 * j][0], s[2 * j][1], ph[0], pl[0]);
                split2(s[2 * j][2], s[2 * j][3], ph[1], pl[1]);
                split2(s[2 * j + 1][0], s[2 * j + 1][1], ph[2], pl[2]);
                split2(s[2 * j + 1][2], s[2 * j + 1][3], ph[3], pl[3]);
#pragma unroll
                for (int p = 0; p < 4; p++) {
                    uint32_t vh[4], vl[4];
                    uint32_t vo = (uint32_t)((j * 16 + vrow0) * ASTRIDE +
                                             16 * p + vcoff) * 2;
                    ldsm4t(vh, base + 2 * KTILE * 2 + vo);
                    ldsm4t(vl, base + 3 * KTILE * 2 + vo);
                    mma16816(o[2 * p],     ph, &vh[0]);
                    mma16816(o[2 * p],     ph, &vl[0]);
                    mma16816(o[2 * p],     pl, &vh[0]);
                    mma16816(o[2 * p + 1], ph, &vh[2]);
                    mma16816(o[2 * p + 1], ph, &vl[2]);
                    mma16816(o[2 * p + 1], pl, &vh[2]);
                }
            }
        }
        __syncthreads();
    }

    // epilogue: write bf16 hi/lo split directly (feeds final GEMM)
    const float inv0 = 1.f / l0, inv1 = 1.f / l1;
    const size_t row = rowbase + q0 + w * 16 + (lane >> 2);
    const size_t col = headoff + (lane & 3) * 2;
#pragma unroll
    for (int t = 0; t < 8; t++) {
        uint32_t h0, l0v, h1, l1v;
        split2(o[t][0] * inv0, o[t][1] * inv0, h0, l0v);
        split2(o[t][2] * inv1, o[t][3] * inv1, h1, l1v);
        *(uint32_t*)&Ohi[row * E_ + col + t * 8] = h0;
        *(uint32_t*)&Olo[row * E_ + col + t * 8] = l0v;
        *(uint32_t*)&Ohi[(row + 8) * E_ + col + t * 8] = h1;
        *(uint32_t*)&Olo[(row + 8) * E_ + col + t * 8] = l1v;
    }
}

// ---------------------------------------------------------------------------
extern "C" void kernel_launch(void* const* d_in, const int* in_sizes, int n_in,
                              void* d_out, int out_size) {
    const float* q_in = (const float*)d_in[0];
    const float* k_in = (const float*)d_in[1];
    const float* v_in = (const float*)d_in[2];
    const float* Wq = (const float*)d_in[3];
    const float* Wk = (const float*)d_in[4];
    const float* Wv = (const float*)d_in[5];
    const float* Wo = (const float*)d_in[6];
    float* out = (float*)d_out;

    float *Q, *K;
    __nv_bfloat16 *Ahi, *Alo, *Whi, *Wlo;
    __nv_bfloat16 *Qhi, *Qlo, *Khi, *Klo, *Vhi, *Vlo;
    cudaGetSymbolAddress((void**)&Q, g_Q);
    cudaGetSymbolAddress((void**)&K, g_K);
    cudaGetSymbolAddress((void**)&Ahi, g_Ahi);
    cudaGetSymbolAddress((void**)&Alo, g_Alo);
    cudaGetSymbolAddress((void**)&Whi, g_Whi);
    cudaGetSymbolAddress((void**)&Wlo, g_Wlo);
    cudaGetSymbolAddress((void**)&Qhi, g_Qhi);
    cudaGetSymbolAddress((void**)&Qlo, g_Qlo);
    cudaGetSymbolAddress((void**)&Khi, g_Khi);
    cudaGetSymbolAddress((void**)&Klo, g_Klo);
    cudaGetSymbolAddress((void**)&Vhi, g_Vhi);
    cudaGetSymbolAddress((void**)&Vlo, g_Vlo);

    cudaFuncSetAttribute(gemm_mma, cudaFuncAttributeMaxDynamicSharedMemorySize,
                         GEMM_SMEM);
    cudaFuncSetAttribute(flash_attn_tc,
                         cudaFuncAttributeMaxDynamicSharedMemorySize, ATTN_SMEM);

    const int nA4 = NELEM / 4;
    const int nW4 = (E_ * E_) / 4;
    const dim3 gg(E_ / 128, MTOT / 128);

    // Q = query @ Wq^T  (fp32 out, rope consumes)
    split_bf16<<<nA4 / 256, 256>>>(q_in, Ahi, Alo, nA4);
    split_bf16<<<nW4 / 256, 256>>>(Wq, Whi, Wlo, nW4);
    gemm_mma<<<gg, 256, GEMM_SMEM>>>(Ahi, Alo, Whi, Wlo, Q, nullptr, nullptr);

    // K = key @ Wk^T
    split_bf16<<<nA4 / 256, 256>>>(k_in, Ahi, Alo, nA4);
    split_bf16<<<nW4 / 256, 256>>>(Wk, Whi, Wlo, nW4);
    gemm_mma<<<gg, 256, GEMM_SMEM>>>(Ahi, Alo, Whi, Wlo, K, nullptr, nullptr);

    // V = value @ Wv^T  (bf16 hi/lo out directly)
    split_bf16<<<nA4 / 256, 256>>>(v_in, Ahi, Alo, nA4);
    split_bf16<<<nW4 / 256, 256>>>(Wv, Whi, Wlo, nW4);
    gemm_mma<<<gg, 256, GEMM_SMEM>>>(Ahi, Alo, Whi, Wlo, nullptr, Vhi, Vlo);

    int rope_threads = 2 * B_ * S_ * H_ * 32;
    rope_split<<<rope_threads / 256, 256>>>(Q, K, Qhi, Qlo, Khi, Klo);

    // attention writes its output pre-split into Ahi/Alo
    flash_attn_tc<<<dim3(S_ / 128, H_, B_), 256, ATTN_SMEM>>>(
        Qhi, Qlo, Khi, Klo, Vhi, Vlo, Ahi, Alo);

    // out = AO @ Wo^T
    split_bf16<<<nW4 / 256, 256>>>(Wo, Whi, Wlo, nW4);
    gemm_mma<<<gg, 256, GEMM_SMEM>>>(Ahi, Alo, Whi, Wlo, out, nullptr, nullptr);
}

// round 7
// speedup vs baseline: 1.0819x; 1.0819x over previous
#include <cuda_runtime.h>
#include <cuda_bf16.h>
#include <math.h>
#include <stdint.h>

#define B_ 4
#define S_ 2048
#define E_ 1024
#define H_ 16
#define D_ 64

static const int MTOT = B_ * S_;          // 8192
#define NELEM (B_ * S_ * E_)              // 8388608

// ---------------- scratch (__device__ globals; no allocs allowed) ----------
__device__ float g_Q[NELEM];
__device__ float g_K[NELEM];
__device__ __nv_bfloat16 g_Ahi[NELEM];
__device__ __nv_bfloat16 g_Alo[NELEM];
__device__ __nv_bfloat16 g_Whi[E_ * E_];
__device__ __nv_bfloat16 g_Wlo[E_ * E_];
__device__ __nv_bfloat16 g_Qhi[NELEM];
__device__ __nv_bfloat16 g_Qlo[NELEM];
__device__ __nv_bfloat16 g_Khi[NELEM];
__device__ __nv_bfloat16 g_Klo[NELEM];
__device__ __nv_bfloat16 g_Vhi[NELEM];
__device__ __nv_bfloat16 g_Vlo[NELEM];

// ---------------- helpers --------------------------------------------------
__device__ __forceinline__ uint32_t smem_u32(const void* p) {
    uint32_t a;
    asm("{ .reg .u64 t; cvta.to.shared.u64 t, %1; cvt.u32.u64 %0, t; }"
        : "=r"(a) : "l"(p));
    return a;
}
__device__ __forceinline__ void cp16(uint32_t saddr, const void* g) {
    asm volatile("cp.async.cg.shared.global [%0], [%1], 16;"
                 :: "r"(saddr), "l"(g) : "memory");
}
__device__ __forceinline__ void ldsm4(uint32_t* r, uint32_t a) {
    asm volatile("ldmatrix.sync.aligned.m8n8.x4.shared.b16 {%0,%1,%2,%3}, [%4];"
                 : "=r"(r[0]), "=r"(r[1]), "=r"(r[2]), "=r"(r[3]) : "r"(a));
}
__device__ __forceinline__ void ldsm4t(uint32_t* r, uint32_t a) {
    asm volatile("ldmatrix.sync.aligned.m8n8.x4.trans.shared.b16 {%0,%1,%2,%3}, [%4];"
                 : "=r"(r[0]), "=r"(r[1]), "=r"(r[2]), "=r"(r[3]) : "r"(a));
}
__device__ __forceinline__ void mma16816(float* c, const uint32_t* a,
                                         const uint32_t* b) {
    asm volatile(
        "mma.sync.aligned.m16n8k16.row.col.f32.bf16.bf16.f32 "
        "{%0,%1,%2,%3}, {%4,%5,%6,%7}, {%8,%9}, {%0,%1,%2,%3};"
        : "+f"(c[0]), "+f"(c[1]), "+f"(c[2]), "+f"(c[3])
        : "r"(a[0]), "r"(a[1]), "r"(a[2]), "r"(a[3]), "r"(b[0]), "r"(b[1]));
}
__device__ __forceinline__ void split2(float x0, float x1, uint32_t& hi,
                                       uint32_t& lo) {
    __nv_bfloat16 h0 = __float2bfloat16(x0);
    __nv_bfloat16 h1 = __float2bfloat16(x1);
    __nv_bfloat16 l0 = __float2bfloat16(x0 - __bfloat162float(h0));
    __nv_bfloat16 l1 = __float2bfloat16(x1 - __bfloat162float(h1));
    hi = (uint32_t)*(uint16_t*)&h0 | ((uint32_t)*(uint16_t*)&h1 << 16);
    lo = (uint32_t)*(uint16_t*)&l0 | ((uint32_t)*(uint16_t*)&l1 << 16);
}

// ---------------- split fp32 -> bf16 hi/lo --------------------------------
__global__ __launch_bounds__(256)
void split_bf16(const float* __restrict__ src, __nv_bfloat16* __restrict__ hi,
                __nv_bfloat16* __restrict__ lo, int n4) {
    int i = blockIdx.x * blockDim.x + threadIdx.x;
    if (i >= n4) return;
    float4 v = ((const float4*)src)[i];
    float f[4] = {v.x, v.y, v.z, v.w};
    __nv_bfloat16 h[4], l[4];
#pragma unroll
    for (int j = 0; j < 4; j++) {
        h[j] = __float2bfloat16(f[j]);
        l[j] = __float2bfloat16(f[j] - __bfloat162float(h[j]));
    }
    ((uint2*)hi)[i] = *(uint2*)h;
    ((uint2*)lo)[i] = *(uint2*)l;
}

// ---------------- mma.sync GEMM ---------------------------------------------
// 128x128 CTA tile, BK=32, 8 warps (2x4), 2-stage cp.async (82KB -> occ 2),
// term-major MMA ordering (acc reuse distance 16).
#define TILEB 10240
#define STAGEB 40960
#define GEMM_SMEM (2 * STAGEB)

__device__ __forceinline__ void load_stage(
    uint32_t sb, int st, const __nv_bfloat16* __restrict__ Ahi,
    const __nv_bfloat16* __restrict__ Alo, const __nv_bfloat16* __restrict__ Bhi,
    const __nv_bfloat16* __restrict__ Blo, int bm, int bn, int k0, int tid) {
    uint32_t s0 = sb + st * STAGEB;
#pragma unroll
    for (int p = 0; p < 2; p++) {
        int chunk = tid + p * 256;
        int row = chunk >> 2;
        int kc = chunk & 3;
        uint32_t soff = (uint32_t)(row * 80 + kc * 16);
        size_t ga = ((size_t)(bm + row) << 10) + k0 + kc * 8;
        size_t gb = ((size_t)(bn + row) << 10) + k0 + kc * 8;
        cp16(s0 + soff,             Ahi + ga);
        cp16(s0 + TILEB + soff,     Alo + ga);
        cp16(s0 + 2 * TILEB + soff, Bhi + gb);
        cp16(s0 + 3 * TILEB + soff, Blo + gb);
    }
}

__global__ __launch_bounds__(256, 2)
void gemm_mma(const __nv_bfloat16* __restrict__ Ahi,
              const __nv_bfloat16* __restrict__ Alo,
              const __nv_bfloat16* __restrict__ Whi,
              const __nv_bfloat16* __restrict__ Wlo,
              float* __restrict__ C,
              __nv_bfloat16* __restrict__ Chi,
              __nv_bfloat16* __restrict__ Clo) {
    extern __shared__ char smem[];
    const uint32_t sb = smem_u32(smem);
    const int tid = threadIdx.x;
    const int lane = tid & 31;
    const int wid = tid >> 5;
    const int wm = wid >> 2;
    const int wn = wid & 3;
    const int bm = blockIdx.y * 128;
    const int bn = blockIdx.x * 128;

    float acc[4][4][4];
#pragma unroll
    for (int i = 0; i < 4; i++)
#pragma unroll
        for (int j = 0; j < 4; j++)
#pragma unroll
            for (int r = 0; r < 4; r++) acc[i][j][r] = 0.f;

    load_stage(sb, 0, Ahi, Alo, Whi, Wlo, bm, bn, 0, tid);
    asm volatile("cp.async.commit_group;" ::: "memory");

    const int NCH = E_ / 32;   // 32
    for (int c = 0; c < NCH; c++) {
        if (c + 1 < NCH) {
            load_stage(sb, (c + 1) & 1, Ahi, Alo, Whi, Wlo, bm, bn,
                       (c + 1) * 32, tid);
            asm volatile("cp.async.commit_group;" ::: "memory");
            asm volatile("cp.async.wait_group 1;" ::: "memory");
        } else {
            asm volatile("cp.async.wait_group 0;" ::: "memory");
        }
        __syncthreads();

        const uint32_t s0 = sb + (c & 1) * STAGEB;
        const uint32_t sAh = s0, sAl = s0 + TILEB;
        const uint32_t sBh = s0 + 2 * TILEB, sBl = s0 + 3 * TILEB;

#pragma unroll
        for (int ks = 0; ks < 32; ks += 16) {
            uint32_t ahi[4][4], alo[4][4], bhi[2][4], blo[2][4];
            const int arow = wm * 64 + (lane & 7) + ((lane >> 3) & 1) * 8;
            const int akk = ks + (lane >> 4) * 8;
#pragma unroll
            for (int mi = 0; mi < 4; mi++) {
                uint32_t ao = (uint32_t)((arow + mi * 16) * 80 + akk * 2);
                ldsm4(ahi[mi], sAh + ao);
                ldsm4(alo[mi], sAl + ao);
            }
            const int brow = wn * 32 + (lane & 7) + ((lane >> 4) & 1) * 8;
            const int bkk = ks + ((lane >> 3) & 1) * 8;
#pragma unroll
            for (int nb = 0; nb < 2; nb++) {
                uint32_t bo = (uint32_t)((brow + nb * 16) * 80 + bkk * 2);
                ldsm4(bhi[nb], sBh + bo);
                ldsm4(blo[nb], sBl + bo);
            }
            // term-major: 16 independent MMAs per pass
#pragma unroll
            for (int mi = 0; mi < 4; mi++)
#pragma unroll
                for (int ni = 0; ni < 4; ni++)
                    mma16816(acc[mi][ni], ahi[mi], &bhi[ni >> 1][(ni & 1) * 2]);
#pragma unroll
            for (int mi = 0; mi < 4; mi++)
#pragma unroll
                for (int ni = 0; ni < 4; ni++)
                    mma16816(acc[mi][ni], ahi[mi], &blo[ni >> 1][(ni & 1) * 2]);
#pragma unroll
            for (int mi = 0; mi < 4; mi++)
#pragma unroll
                for (int ni = 0; ni < 4; ni++)
                    mma16816(acc[mi][ni], alo[mi], &bhi[ni >> 1][(ni & 1) * 2]);
        }
        __syncthreads();
    }

    const int r0 = bm + wm * 64 + (lane >> 2);
    const int c0 = bn + wn * 32 + (lane & 3) * 2;
    if (C) {
#pragma unroll
        for (int mi = 0; mi < 4; mi++)
#pragma unroll
            for (int ni = 0; ni < 4; ni++) {
                int row = r0 + mi * 16;
                int col = c0 + ni * 8;
                *(float2*)&C[(size_t)row * E_ + col] =
                    make_float2(acc[mi][ni][0], acc[mi][ni][1]);
                *(float2*)&C[(size_t)(row + 8) * E_ + col] =
                    make_float2(acc[mi][ni][2], acc[mi][ni][3]);
            }
    }
    if (Chi) {
#pragma unroll
        for (int mi = 0; mi < 4; mi++)
#pragma unroll
            for (int ni = 0; ni < 4; ni++) {
                int row = r0 + mi * 16;
                int col = c0 + ni * 8;
                uint32_t h0, l0v, h1, l1v;
                split2(acc[mi][ni][0], acc[mi][ni][1], h0, l0v);
                split2(acc[mi][ni][2], acc[mi][ni][3], h1, l1v);
                *(uint32_t*)&Chi[(size_t)row * E_ + col] = h0;
                *(uint32_t*)&Clo[(size_t)row * E_ + col] = l0v;
                *(uint32_t*)&Chi[(size_t)(row + 8) * E_ + col] = h1;
                *(uint32_t*)&Clo[(size_t)(row + 8) * E_ + col] = l1v;
            }
    }
}

// ---------------- RoPE + bf16 split. Q gets 1/8 scale folded in. ----------
__global__ void rope_split(const float* __restrict__ Q, const float* __restrict__ K,
                           __nv_bfloat16* __restrict__ Qhi, __nv_bfloat16* __restrict__ Qlo,
                           __nv_bfloat16* __restrict__ Khi, __nv_bfloat16* __restrict__ Klo) {
    const int per = B_ * S_ * H_ * 32;
    int idx = blockIdx.x * blockDim.x + threadIdx.x;
    if (idx >= 2 * per) return;
    bool isQ = idx < per;
    int r = isQ ? idx : idx - per;
    int i = r & 31;
    int hh = (r >> 5) & (H_ - 1);
    int s = (r >> 9) & (S_ - 1);
    int b = r >> 20;

    float inv_freq = __expf(-(float)i * (logf(10000.0f) / 32.0f));
    float ang = (float)s * inv_freq;
    float sn, cs;
    sincosf(ang, &sn, &cs);

    size_t base = ((size_t)(b * S_ + s)) * E_ + hh * D_ + i;
    const float* src = isQ ? Q : K;
    float x1 = src[base];
    float x2 = src[base + 32];
    float y1 = x1 * cs - x2 * sn;
    float y2 = x2 * cs + x1 * sn;
    if (isQ) { y1 *= 0.125f; y2 *= 0.125f; }

    __nv_bfloat16* hi = isQ ? Qhi : Khi;
    __nv_bfloat16* lo = isQ ? Qlo : Klo;
    __nv_bfloat16 h1 = __float2bfloat16(y1);
    __nv_bfloat16 h2 = __float2bfloat16(y2);
    hi[base] = h1;
    hi[base + 32] = h2;
    lo[base] = __float2bfloat16(y1 - __bfloat162float(h1));
    lo[base + 32] = __float2bfloat16(y2 - __bfloat162float(h2));
}

// ---------------- tensor-core causal flash attention ----------------------
#define ASTRIDE 72
#define KTILE (64 * ASTRIDE)
#define ASTAGE (4 * KTILE)
#define ATTN_SMEM (2 * ASTAGE * 2)

__device__ __forceinline__ void load_kv(
    uint32_t sb, const __nv_bfloat16* __restrict__ Khi,
    const __nv_bfloat16* __restrict__ Klo, const __nv_bfloat16* __restrict__ Vhi,
    const __nv_bfloat16* __restrict__ Vlo, size_t rowbase, size_t headoff,
    int k0, int tid) {
#pragma unroll
    for (int p = 0; p < 2; p++) {
        int chunk = tid + p * 256;
        int row = chunk >> 3;
        int c8 = chunk & 7;
        size_t g = (rowbase + k0 + row) * E_ + headoff + c8 * 8;
        uint32_t so = (uint32_t)(row * ASTRIDE + c8 * 8) * 2;
        cp16(sb + so,                 Khi + g);
        cp16(sb + KTILE * 2 + so,     Klo + g);
        cp16(sb + 2 * KTILE * 2 + so, Vhi + g);
        cp16(sb + 3 * KTILE * 2 + so, Vlo + g);
    }
}

__global__ __launch_bounds__(256, 2)
void flash_attn_tc(const __nv_bfloat16* __restrict__ Qhi,
                   const __nv_bfloat16* __restrict__ Qlo,
                   const __nv_bfloat16* __restrict__ Khi,
                   const __nv_bfloat16* __restrict__ Klo,
                   const __nv_bfloat16* __restrict__ Vhi,
                   const __nv_bfloat16* __restrict__ Vlo,
                   __nv_bfloat16* __restrict__ Ohi,
                   __nv_bfloat16* __restrict__ Olo) {
    extern __shared__ char smem[];
    const uint32_t sb = smem_u32(smem);
    const int tid = threadIdx.x;
    const int lane = tid & 31;
    const int w = tid >> 5;
    const int qt = gridDim.x - 1 - blockIdx.x;
    const int h = blockIdx.y;
    const int b = blockIdx.z;
    const int q0 = qt * 128;
    const size_t rowbase = (size_t)(b * S_);
    const size_t headoff = (size_t)h * D_;

#pragma unroll
    for (int p = 0; p < 4; p++) {
        int chunk = tid + p * 256;
        int row = chunk >> 3;
        int c8 = chunk & 7;
        size_t g = (rowbase + q0 + row) * E_ + headoff + c8 * 8;
        uint32_t so = (uint32_t)(row * ASTRIDE + c8 * 8) * 2;
        cp16(sb + so, Qhi + g);
        cp16(sb + 2 * KTILE * 2 + so, Qlo + g);
    }
    asm volatile("cp.async.commit_group;" ::: "memory");
    asm volatile("cp.async.wait_group 0;" ::: "memory");
    __syncthreads();

    uint32_t qh[4][4], ql[4][4];
    {
        const int arow = w * 16 + (lane & 7) + ((lane >> 3) & 1) * 8;
#pragma unroll
        for (int ks = 0; ks < 4; ks++) {
            const int koff = ks * 16 + (lane >> 4) * 8;
            uint32_t ao = (uint32_t)(arow * ASTRIDE + koff) * 2;
            ldsm4(qh[ks], sb + ao);
            ldsm4(ql[ks], sb + 2 * KTILE * 2 + ao);
        }
    }
    __syncthreads();

    float m0 = -INFINITY, m1 = -INFINITY, l0 = 0.f, l1 = 0.f;
    float o[8][4];
#pragma unroll
    for (int t = 0; t < 8; t++)
#pragma unroll
        for (int r = 0; r < 4; r++) o[t][r] = 0.f;

    const int nkb = 2 * (qt + 1);
    load_kv(sb, Khi, Klo, Vhi, Vlo, rowbase, headoff, 0, tid);
    asm volatile("cp.async.commit_group;" ::: "memory");

    for (int kt = 0; kt < nkb; kt++) {
        if (kt + 1 < nkb) {
            load_kv(sb + ((kt + 1) & 1) * ASTAGE * 2, Khi, Klo, Vhi, Vlo,
                    rowbase, headoff, (kt + 1) * 64, tid);
            asm volatile("cp.async.commit_group;" ::: "memory");
            asm volatile("cp.async.wait_group 1;" ::: "memory");
        } else {
            asm volatile("cp.async.wait_group 0;" ::: "memory");
        }
        __syncthreads();

        const int k0 = kt * 64;
        const bool skip = (q0 + w * 16 + 15) < k0;
        if (!skip) {
            const uint32_t base = sb + (kt & 1) * ASTAGE * 2;
            float s[8][4];
#pragma unroll
            for (int t = 0; t < 8; t++)
#pragma unroll
                for (int r = 0; r < 4; r++) s[t][r] = 0.f;

            const int nrow = (lane & 7) + ((lane >> 4) & 1) * 8;
#pragma unroll
            for (int ks = 0; ks < 4; ks++) {
                const int koff = ks * 16 + ((lane >> 3) & 1) * 8;
#pragma unroll
                for (int p = 0; p < 4; p++) {
                    uint32_t kh[4], kl[4];
                    uint32_t ao = (uint32_t)((16 * p + nrow) * ASTRIDE + koff) * 2;
                    ldsm4(kh, base + ao);
                    ldsm4(kl, base + KTILE * 2 + ao);
                    mma16816(s[2 * p],     qh[ks], &kh[0]);
                    mma16816(s[2 * p],     qh[ks], &kl[0]);
                    mma16816(s[2 * p],     ql[ks], &kh[0]);
                    mma16816(s[2 * p + 1], qh[ks], &kh[2]);
                    mma16816(s[2 * p + 1], qh[ks], &kl[2]);
                    mma16816(s[2 * p + 1], ql[ks], &kh[2]);
                }
            }

            const int row0 = q0 + w * 16 + (lane >> 2);
            if (kt >= 2 * qt) {
#pragma unroll
                for (int t = 0; t < 8; t++) {
                    int col = k0 + t * 8 + (lane & 3) * 2;
                    if (col > row0)         s[t][0] = -1e30f;
                    if (col + 1 > row0)     s[t][1] = -1e30f;
                    if (col > row0 + 8)     s[t][2] = -1e30f;
                    if (col + 1 > row0 + 8) s[t][3] = -1e30f;
                }
            }

            float mx0 = -INFINITY, mx1 = -INFINITY;
#pragma unroll
            for (int t = 0; t < 8; t++) {
                mx0 = fmaxf(mx0, fmaxf(s[t][0], s[t][1]));
                mx1 = fmaxf(mx1, fmaxf(s[t][2], s[t][3]));
            }
#pragma unroll
            for (int off = 1; off <= 2; off <<= 1) {
                mx0 = fmaxf(mx0, __shfl_xor_sync(0xffffffffu, mx0, off));
                mx1 = fmaxf(mx1, __shfl_xor_sync(0xffffffffu, mx1, off));
            }
            float mn0 = fmaxf(m0, mx0), mn1 = fmaxf(m1, mx1);
            float al0 = __expf(m0 - mn0), al1 = __expf(m1 - mn1);
            m0 = mn0; m1 = mn1;
            float rs0 = 0.f, rs1 = 0.f;
#pragma unroll
            for (int t = 0; t < 8; t++) {
                s[t][0] = __expf(s[t][0] - mn0);
                s[t][1] = __expf(s[t][1] - mn0);
                s[t][2] = __expf(s[t][2] - mn1);
                s[t][3] = __expf(s[t][3] - mn1);
                rs0 += s[t][0] + s[t][1];
                rs1 += s[t][2] + s[t][3];
            }
#pragma unroll
            for (int off = 1; off <= 2; off <<= 1) {
                rs0 += __shfl_xor_sync(0xffffffffu, rs0, off);
                rs1 += __shfl_xor_sync(0xffffffffu, rs1, off);
            }
            l0 = l0 * al0 + rs0;
            l1 = l1 * al1 + rs1;
#pragma unroll
            for (int t = 0; t < 8; t++) {
                o[t][0] *= al0; o[t][1] *= al0;
                o[t][2] *= al1; o[t][3] *= al1;
            }

            const int vrow0 = lane & 15;
            const int vcoff = (lane >> 4) * 8;
#pragma unroll
            for (int j = 0; j < 4; j++) {
                uint32_t ph[4], pl[4];
                split2(s[2 * j][0], s[2 * j][1], ph[0], pl[0]);
                split2(s[2 * j][2], s[2 * j][3], ph[1], pl[1]);
                split2(s[2 * j + 1][0], s[2 * j + 1][1], ph[2], pl[2]);
                split2(s[2 * j + 1][2], s[2 * j + 1][3], ph[3], pl[3]);
#pragma unroll
                for (int p = 0; p < 4; p++) {
                    uint32_t vh[4], vl[4];
                    uint32_t vo = (uint32_t)((j * 16 + vrow0) * ASTRIDE +
                                             16 * p + vcoff) * 2;
                    ldsm4t(vh, base + 2 * KTILE * 2 + vo);
                    ldsm4t(vl, base + 3 * KTILE * 2 + vo);
                    mma16816(o[2 * p],     ph, &vh[0]);
                    mma16816(o[2 * p],     ph, &vl[0]);
                    mma16816(o[2 * p],     pl, &vh[0]);
                    mma16816(o[2 * p + 1], ph, &vh[2]);
                    mma16816(o[2 * p + 1], ph, &vl[2]);
                    mma16816(o[2 * p + 1], pl, &vh[2]);
                }
            }
        }
        __syncthreads();
    }

    // epilogue: write bf16 hi/lo split directly (feeds final GEMM)
    const float inv0 = 1.f / l0, inv1 = 1.f / l1;
    const size_t row = rowbase + q0 + w * 16 + (lane >> 2);
    const size_t col = headoff + (lane & 3) * 2;
#pragma unroll
    for (int t = 0; t < 8; t++) {
        uint32_t h0, l0v, h1, l1v;
        split2(o[t][0] * inv0, o[t][1] * inv0, h0, l0v);
        split2(o[t][2] * inv1, o[t][3] * inv1, h1, l1v);
        *(uint32_t*)&Ohi[row * E_ + col + t * 8] = h0;
        *(uint32_t*)&Olo[row * E_ + col + t * 8] = l0v;
        *(uint32_t*)&Ohi[(row + 8) * E_ + col + t * 8] = h1;
        *(uint32_t*)&Olo[(row + 8) * E_ + col + t * 8] = l1v;
    }
}

// ---------------------------------------------------------------------------
extern "C" void kernel_launch(void* const* d_in, const int* in_sizes, int n_in,
                              void* d_out, int out_size) {
    const float* q_in = (const float*)d_in[0];
    const float* k_in = (const float*)d_in[1];
    const float* v_in = (const float*)d_in[2];
    const float* Wq = (const float*)d_in[3];
    const float* Wk = (const float*)d_in[4];
    const float* Wv = (const float*)d_in[5];
    const float* Wo = (const float*)d_in[6];
    float* out = (float*)d_out;

    float *Q, *K;
    __nv_bfloat16 *Ahi, *Alo, *Whi, *Wlo;
    __nv_bfloat16 *Qhi, *Qlo, *Khi, *Klo, *Vhi, *Vlo;
    cudaGetSymbolAddress((void**)&Q, g_Q);
    cudaGetSymbolAddress((void**)&K, g_K);
    cudaGetSymbolAddress((void**)&Ahi, g_Ahi);
    cudaGetSymbolAddress((void**)&Alo, g_Alo);
    cudaGetSymbolAddress((void**)&Whi, g_Whi);
    cudaGetSymbolAddress((void**)&Wlo, g_Wlo);
    cudaGetSymbolAddress((void**)&Qhi, g_Qhi);
    cudaGetSymbolAddress((void**)&Qlo, g_Qlo);
    cudaGetSymbolAddress((void**)&Khi, g_Khi);
    cudaGetSymbolAddress((void**)&Klo, g_Klo);
    cudaGetSymbolAddress((void**)&Vhi, g_Vhi);
    cudaGetSymbolAddress((void**)&Vlo, g_Vlo);

    cudaFuncSetAttribute(gemm_mma, cudaFuncAttributeMaxDynamicSharedMemorySize,
                         GEMM_SMEM);
    cudaFuncSetAttribute(flash_attn_tc,
                         cudaFuncAttributeMaxDynamicSharedMemorySize, ATTN_SMEM);

    const int nA4 = NELEM / 4;
    const int nW4 = (E_ * E_) / 4;
    const dim3 gg(E_ / 128, MTOT / 128);

    // Q = query @ Wq^T  (fp32 out, rope consumes)
    split_bf16<<<nA4 / 256, 256>>>(q_in, Ahi, Alo, nA4);
    split_bf16<<<nW4 / 256, 256>>>(Wq, Whi, Wlo, nW4);
    gemm_mma<<<gg, 256, GEMM_SMEM>>>(Ahi, Alo, Whi, Wlo, Q, nullptr, nullptr);

    // K = key @ Wk^T
    split_bf16<<<nA4 / 256, 256>>>(k_in, Ahi, Alo, nA4);
    split_bf16<<<nW4 / 256, 256>>>(Wk, Whi, Wlo, nW4);
    gemm_mma<<<gg, 256, GEMM_SMEM>>>(Ahi, Alo, Whi, Wlo, K, nullptr, nullptr);

    // V = value @ Wv^T  (bf16 hi/lo out directly)
    split_bf16<<<nA4 / 256, 256>>>(v_in, Ahi, Alo, nA4);
    split_bf16<<<nW4 / 256, 256>>>(Wv, Whi, Wlo, nW4);
    gemm_mma<<<gg, 256, GEMM_SMEM>>>(Ahi, Alo, Whi, Wlo, nullptr, Vhi, Vlo);

    int rope_threads = 2 * B_ * S_ * H_ * 32;
    rope_split<<<rope_threads / 256, 256>>>(Q, K, Qhi, Qlo, Khi, Klo);

    // attention writes its output pre-split into Ahi/Alo
    flash_attn_tc<<<dim3(S_ / 128, H_, B_), 256, ATTN_SMEM>>>(
        Qhi, Qlo, Khi, Klo, Vhi, Vlo, Ahi, Alo);

    // out = AO @ Wo^T
    split_bf16<<<nW4 / 256, 256>>>(Wo, Whi, Wlo, nW4);
    gemm_mma<<<gg, 256, GEMM_SMEM>>>(Ahi, Alo, Whi, Wlo, out, nullptr, nullptr);
}

// round 8
// speedup vs baseline: 1.1293x; 1.0438x over previous
#include <cuda_runtime.h>
#include <cuda_bf16.h>
#include <math.h>
#include <stdint.h>

#define B_ 4
#define S_ 2048
#define E_ 1024
#define H_ 16
#define D_ 64

static const int MTOT = B_ * S_;          // 8192
#define NELEM (B_ * S_ * E_)              // 8388608
#define NW (E_ * E_)

// ---------------- scratch (__device__ globals; no allocs allowed) ----------
__device__ float g_Q[NELEM];
__device__ float g_K[NELEM];
__device__ __nv_bfloat16 g_Ahi[NELEM];
__device__ __nv_bfloat16 g_Alo[NELEM];
__device__ __nv_bfloat16 g_Thi[NELEM];   // v-projection A staging
__device__ __nv_bfloat16 g_Tlo[NELEM];
__device__ __nv_bfloat16 g_Whi[NW];      // Wq
__device__ __nv_bfloat16 g_Wlo[NW];
__device__ __nv_bfloat16 g_W2hi[NW];     // Wk
__device__ __nv_bfloat16 g_W2lo[NW];
__device__ __nv_bfloat16 g_W3hi[NW];     // Wv
__device__ __nv_bfloat16 g_W3lo[NW];
__device__ __nv_bfloat16 g_W4hi[NW];     // Wo
__device__ __nv_bfloat16 g_W4lo[NW];
__device__ __nv_bfloat16 g_Qhi[NELEM];
__device__ __nv_bfloat16 g_Qlo[NELEM];
__device__ __nv_bfloat16 g_Khi[NELEM];
__device__ __nv_bfloat16 g_Klo[NELEM];
__device__ __nv_bfloat16 g_Vhi[NELEM];
__device__ __nv_bfloat16 g_Vlo[NELEM];

// ---------------- helpers --------------------------------------------------
__device__ __forceinline__ uint32_t smem_u32(const void* p) {
    uint32_t a;
    asm("{ .reg .u64 t; cvta.to.shared.u64 t, %1; cvt.u32.u64 %0, t; }"
        : "=r"(a) : "l"(p));
    return a;
}
__device__ __forceinline__ void cp16(uint32_t saddr, const void* g) {
    asm volatile("cp.async.cg.shared.global [%0], [%1], 16;"
                 :: "r"(saddr), "l"(g) : "memory");
}
__device__ __forceinline__ void ldsm4(uint32_t* r, uint32_t a) {
    asm volatile("ldmatrix.sync.aligned.m8n8.x4.shared.b16 {%0,%1,%2,%3}, [%4];"
                 : "=r"(r[0]), "=r"(r[1]), "=r"(r[2]), "=r"(r[3]) : "r"(a));
}
__device__ __forceinline__ void ldsm4t(uint32_t* r, uint32_t a) {
    asm volatile("ldmatrix.sync.aligned.m8n8.x4.trans.shared.b16 {%0,%1,%2,%3}, [%4];"
                 : "=r"(r[0]), "=r"(r[1]), "=r"(r[2]), "=r"(r[3]) : "r"(a));
}
__device__ __forceinline__ void mma16816(float* c, const uint32_t* a,
                                         const uint32_t* b) {
    asm volatile(
        "mma.sync.aligned.m16n8k16.row.col.f32.bf16.bf16.f32 "
        "{%0,%1,%2,%3}, {%4,%5,%6,%7}, {%8,%9}, {%0,%1,%2,%3};"
        : "+f"(c[0]), "+f"(c[1]), "+f"(c[2]), "+f"(c[3])
        : "r"(a[0]), "r"(a[1]), "r"(a[2]), "r"(a[3]), "r"(b[0]), "r"(b[1]));
}
__device__ __forceinline__ void split2(float x0, float x1, uint32_t& hi,
                                       uint32_t& lo) {
    __nv_bfloat16 h0 = __float2bfloat16(x0);
    __nv_bfloat16 h1 = __float2bfloat16(x1);
    __nv_bfloat16 l0 = __float2bfloat16(x0 - __bfloat162float(h0));
    __nv_bfloat16 l1 = __float2bfloat16(x1 - __bfloat162float(h1));
    hi = (uint32_t)*(uint16_t*)&h0 | ((uint32_t)*(uint16_t*)&h1 << 16);
    lo = (uint32_t)*(uint16_t*)&l0 | ((uint32_t)*(uint16_t*)&l1 << 16);
}
__device__ __forceinline__ void split4(const float* f, __nv_bfloat16* h,
                                       __nv_bfloat16* l) {
#pragma unroll
    for (int j = 0; j < 4; j++) {
        h[j] = __float2bfloat16(f[j]);
        l[j] = __float2bfloat16(f[j] - __bfloat162float(h[j]));
    }
}

// ---------------- fused split kernels --------------------------------------
// All four weight matrices in one launch. nW4 = 2^18 quads per weight.
__global__ __launch_bounds__(256)
void split_W_all(const float* __restrict__ W0, const float* __restrict__ W1,
                 const float* __restrict__ W2, const float* __restrict__ W3) {
    int i = blockIdx.x * 256 + threadIdx.x;
    int which = i >> 18;
    int j = i & 0x3FFFF;
    const float* src = which == 0 ? W0 : which == 1 ? W1 : which == 2 ? W2 : W3;
    __nv_bfloat16* hi = which == 0 ? g_Whi : which == 1 ? g_W2hi
                       : which == 2 ? g_W3hi : g_W4hi;
    __nv_bfloat16* lo = which == 0 ? g_Wlo : which == 1 ? g_W2lo
                       : which == 2 ? g_W3lo : g_W4lo;
    float4 v = ((const float4*)src)[j];
    float f[4] = {v.x, v.y, v.z, v.w};
    __nv_bfloat16 h[4], l[4];
    split4(f, h, l);
    ((uint2*)hi)[j] = *(uint2*)h;
    ((uint2*)lo)[j] = *(uint2*)l;
}

// q,k,v activations in one launch. nA4 = 2^21 quads per tensor.
// q -> Ahi/Alo, k -> Khi/Klo (staging, consumed by gemmK before rope
// overwrites), v -> Thi/Tlo.
__global__ __launch_bounds__(256)
void split_A_all(const float* __restrict__ Aq, const float* __restrict__ Ak,
                 const float* __restrict__ Av) {
    int i = blockIdx.x * 256 + threadIdx.x;
    int which = i >> 21;
    int j = i & 0x1FFFFF;
    const float* src = which == 0 ? Aq : which == 1 ? Ak : Av;
    __nv_bfloat16* hi = which == 0 ? g_Ahi : which == 1 ? g_Khi : g_Thi;
    __nv_bfloat16* lo = which == 0 ? g_Alo : which == 1 ? g_Klo : g_Tlo;
    float4 v = ((const float4*)src)[j];
    float f[4] = {v.x, v.y, v.z, v.w};
    __nv_bfloat16 h[4], l[4];
    split4(f, h, l);
    ((uint2*)hi)[j] = *(uint2*)h;
    ((uint2*)lo)[j] = *(uint2*)l;
}

// ---------------- mma.sync GEMM ---------------------------------------------
// 128x128 CTA tile, BK=32, 8 warps (2x4), 2-stage cp.async (82KB -> occ 2).
// A fragments streamed per mi (live regs ~100 -> no spills at 128-reg cap).
#define TILEB 10240
#define STAGEB 40960
#define GEMM_SMEM (2 * STAGEB)

__device__ __forceinline__ void load_stage(
    uint32_t sb, int st, const __nv_bfloat16* __restrict__ Ahi,
    const __nv_bfloat16* __restrict__ Alo, const __nv_bfloat16* __restrict__ Bhi,
    const __nv_bfloat16* __restrict__ Blo, int bm, int bn, int k0, int tid) {
    uint32_t s0 = sb + st * STAGEB;
#pragma unroll
    for (int p = 0; p < 2; p++) {
        int chunk = tid + p * 256;
        int row = chunk >> 2;
        int kc = chunk & 3;
        uint32_t soff = (uint32_t)(row * 80 + kc * 16);
        size_t ga = ((size_t)(bm + row) << 10) + k0 + kc * 8;
        size_t gb = ((size_t)(bn + row) << 10) + k0 + kc * 8;
        cp16(s0 + soff,             Ahi + ga);
        cp16(s0 + TILEB + soff,     Alo + ga);
        cp16(s0 + 2 * TILEB + soff, Bhi + gb);
        cp16(s0 + 3 * TILEB + soff, Blo + gb);
    }
}

__global__ __launch_bounds__(256, 2)
void gemm_mma(const __nv_bfloat16* __restrict__ Ahi,
              const __nv_bfloat16* __restrict__ Alo,
              const __nv_bfloat16* __restrict__ Whi,
              const __nv_bfloat16* __restrict__ Wlo,
              float* __restrict__ C,
              __nv_bfloat16* __restrict__ Chi,
              __nv_bfloat16* __restrict__ Clo) {
    extern __shared__ char smem[];
    const uint32_t sb = smem_u32(smem);
    const int tid = threadIdx.x;
    const int lane = tid & 31;
    const int wid = tid >> 5;
    const int wm = wid >> 2;
    const int wn = wid & 3;
    const int bm = blockIdx.y * 128;
    const int bn = blockIdx.x * 128;

    float acc[4][4][4];
#pragma unroll
    for (int i = 0; i < 4; i++)
#pragma unroll
        for (int j = 0; j < 4; j++)
#pragma unroll
            for (int r = 0; r < 4; r++) acc[i][j][r] = 0.f;

    load_stage(sb, 0, Ahi, Alo, Whi, Wlo, bm, bn, 0, tid);
    asm volatile("cp.async.commit_group;" ::: "memory");

    const int NCH = E_ / 32;   // 32
    for (int c = 0; c < NCH; c++) {
        if (c + 1 < NCH) {
            load_stage(sb, (c + 1) & 1, Ahi, Alo, Whi, Wlo, bm, bn,
                       (c + 1) * 32, tid);
            asm volatile("cp.async.commit_group;" ::: "memory");
            asm volatile("cp.async.wait_group 1;" ::: "memory");
        } else {
            asm volatile("cp.async.wait_group 0;" ::: "memory");
        }
        __syncthreads();

        const uint32_t s0 = sb + (c & 1) * STAGEB;
        const uint32_t sAh = s0, sAl = s0 + TILEB;
        const uint32_t sBh = s0 + 2 * TILEB, sBl = s0 + 3 * TILEB;

#pragma unroll
        for (int ks = 0; ks < 32; ks += 16) {
            uint32_t bhi[2][4], blo[2][4];
            const int brow = wn * 32 + (lane & 7) + ((lane >> 4) & 1) * 8;
            const int bkk = ks + ((lane >> 3) & 1) * 8;
#pragma unroll
            for (int nb = 0; nb < 2; nb++) {
                uint32_t bo = (uint32_t)((brow + nb * 16) * 80 + bkk * 2);
                ldsm4(bhi[nb], sBh + bo);
                ldsm4(blo[nb], sBl + bo);
            }
            const int arow = wm * 64 + (lane & 7) + ((lane >> 3) & 1) * 8;
            const int akk = ks + (lane >> 4) * 8;
            // stream A fragments: only one mi's ahi/alo live at a time
#pragma unroll
            for (int mi = 0; mi < 4; mi++) {
                uint32_t ahi[4], alo[4];
                uint32_t ao = (uint32_t)((arow + mi * 16) * 80 + akk * 2);
                ldsm4(ahi, sAh + ao);
                ldsm4(alo, sAl + ao);
#pragma unroll
                for (int ni = 0; ni < 4; ni++)
                    mma16816(acc[mi][ni], ahi, &bhi[ni >> 1][(ni & 1) * 2]);
#pragma unroll
                for (int ni = 0; ni < 4; ni++)
                    mma16816(acc[mi][ni], ahi, &blo[ni >> 1][(ni & 1) * 2]);
#pragma unroll
                for (int ni = 0; ni < 4; ni++)
                    mma16816(acc[mi][ni], alo, &bhi[ni >> 1][(ni & 1) * 2]);
            }
        }
        __syncthreads();
    }

    const int r0 = bm + wm * 64 + (lane >> 2);
    const int c0 = bn + wn * 32 + (lane & 3) * 2;
    if (C) {
#pragma unroll
        for (int mi = 0; mi < 4; mi++)
#pragma unroll
            for (int ni = 0; ni < 4; ni++) {
                int row = r0 + mi * 16;
                int col = c0 + ni * 8;
                *(float2*)&C[(size_t)row * E_ + col] =
                    make_float2(acc[mi][ni][0], acc[mi][ni][1]);
                *(float2*)&C[(size_t)(row + 8) * E_ + col] =
                    make_float2(acc[mi][ni][2], acc[mi][ni][3]);
            }
    }
    if (Chi) {
#pragma unroll
        for (int mi = 0; mi < 4; mi++)
#pragma unroll
            for (int ni = 0; ni < 4; ni++) {
                int row = r0 + mi * 16;
                int col = c0 + ni * 8;
                uint32_t h0, l0v, h1, l1v;
                split2(acc[mi][ni][0], acc[mi][ni][1], h0, l0v);
                split2(acc[mi][ni][2], acc[mi][ni][3], h1, l1v);
                *(uint32_t*)&Chi[(size_t)row * E_ + col] = h0;
                *(uint32_t*)&Clo[(size_t)row * E_ + col] = l0v;
                *(uint32_t*)&Chi[(size_t)(row + 8) * E_ + col] = h1;
                *(uint32_t*)&Clo[(size_t)(row + 8) * E_ + col] = l1v;
            }
    }
}

// ---------------- RoPE + bf16 split. Q gets 1/8 scale folded in. ----------
__global__ void rope_split(const float* __restrict__ Q, const float* __restrict__ K,
                           __nv_bfloat16* __restrict__ Qhi, __nv_bfloat16* __restrict__ Qlo,
                           __nv_bfloat16* __restrict__ Khi, __nv_bfloat16* __restrict__ Klo) {
    const int per = B_ * S_ * H_ * 32;
    int idx = blockIdx.x * blockDim.x + threadIdx.x;
    if (idx >= 2 * per) return;
    bool isQ = idx < per;
    int r = isQ ? idx : idx - per;
    int i = r & 31;
    int hh = (r >> 5) & (H_ - 1);
    int s = (r >> 9) & (S_ - 1);
    int b = r >> 20;

    float inv_freq = __expf(-(float)i * (logf(10000.0f) / 32.0f));
    float ang = (float)s * inv_freq;
    float sn, cs;
    sincosf(ang, &sn, &cs);

    size_t base = ((size_t)(b * S_ + s)) * E_ + hh * D_ + i;
    const float* src = isQ ? Q : K;
    float x1 = src[base];
    float x2 = src[base + 32];
    float y1 = x1 * cs - x2 * sn;
    float y2 = x2 * cs + x1 * sn;
    if (isQ) { y1 *= 0.125f; y2 *= 0.125f; }

    __nv_bfloat16* hi = isQ ? Qhi : Khi;
    __nv_bfloat16* lo = isQ ? Qlo : Klo;
    __nv_bfloat16 h1 = __float2bfloat16(y1);
    __nv_bfloat16 h2 = __float2bfloat16(y2);
    hi[base] = h1;
    hi[base + 32] = h2;
    lo[base] = __float2bfloat16(y1 - __bfloat162float(h1));
    lo[base + 32] = __float2bfloat16(y2 - __bfloat162float(h2));
}

// ---------------- tensor-core causal flash attention ----------------------
#define ASTRIDE 72
#define KTILE (64 * ASTRIDE)
#define ASTAGE (4 * KTILE)
#define ATTN_SMEM (2 * ASTAGE * 2)

__device__ __forceinline__ void load_kv(
    uint32_t sb, const __nv_bfloat16* __restrict__ Khi,
    const __nv_bfloat16* __restrict__ Klo, const __nv_bfloat16* __restrict__ Vhi,
    const __nv_bfloat16* __restrict__ Vlo, size_t rowbase, size_t headoff,
    int k0, int tid) {
#pragma unroll
    for (int p = 0; p < 2; p++) {
        int chunk = tid + p * 256;
        int row = chunk >> 3;
        int c8 = chunk & 7;
        size_t g = (rowbase + k0 + row) * E_ + headoff + c8 * 8;
        uint32_t so = (uint32_t)(row * ASTRIDE + c8 * 8) * 2;
        cp16(sb + so,                 Khi + g);
        cp16(sb + KTILE * 2 + so,     Klo + g);
        cp16(sb + 2 * KTILE * 2 + so, Vhi + g);
        cp16(sb + 3 * KTILE * 2 + so, Vlo + g);
    }
}

__global__ __launch_bounds__(256, 2)
void flash_attn_tc(const __nv_bfloat16* __restrict__ Qhi,
                   const __nv_bfloat16* __restrict__ Qlo,
                   const __nv_bfloat16* __restrict__ Khi,
                   const __nv_bfloat16* __restrict__ Klo,
                   const __nv_bfloat16* __restrict__ Vhi,
                   const __nv_bfloat16* __restrict__ Vlo,
                   __nv_bfloat16* __restrict__ Ohi,
                   __nv_bfloat16* __restrict__ Olo) {
    extern __shared__ char smem[];
    const uint32_t sb = smem_u32(smem);
    const int tid = threadIdx.x;
    const int lane = tid & 31;
    const int w = tid >> 5;
    const int qt = gridDim.x - 1 - blockIdx.x;
    const int h = blockIdx.y;
    const int b = blockIdx.z;
    const int q0 = qt * 128;
    const size_t rowbase = (size_t)(b * S_);
    const size_t headoff = (size_t)h * D_;

#pragma unroll
    for (int p = 0; p < 4; p++) {
        int chunk = tid + p * 256;
        int row = chunk >> 3;
        int c8 = chunk & 7;
        size_t g = (rowbase + q0 + row) * E_ + headoff + c8 * 8;
        uint32_t so = (uint32_t)(row * ASTRIDE + c8 * 8) * 2;
        cp16(sb + so, Qhi + g);
        cp16(sb + 2 * KTILE * 2 + so, Qlo + g);
    }
    asm volatile("cp.async.commit_group;" ::: "memory");
    asm volatile("cp.async.wait_group 0;" ::: "memory");
    __syncthreads();

    uint32_t qh[4][4], ql[4][4];
    {
        const int arow = w * 16 + (lane & 7) + ((lane >> 3) & 1) * 8;
#pragma unroll
        for (int ks = 0; ks < 4; ks++) {
            const int koff = ks * 16 + (lane >> 4) * 8;
            uint32_t ao = (uint32_t)(arow * ASTRIDE + koff) * 2;
            ldsm4(qh[ks], sb + ao);
            ldsm4(ql[ks], sb + 2 * KTILE * 2 + ao);
        }
    }
    __syncthreads();

    float m0 = -INFINITY, m1 = -INFINITY, l0 = 0.f, l1 = 0.f;
    float o[8][4];
#pragma unroll
    for (int t = 0; t < 8; t++)
#pragma unroll
        for (int r = 0; r < 4; r++) o[t][r] = 0.f;

    const int nkb = 2 * (qt + 1);
    load_kv(sb, Khi, Klo, Vhi, Vlo, rowbase, headoff, 0, tid);
    asm volatile("cp.async.commit_group;" ::: "memory");

    for (int kt = 0; kt < nkb; kt++) {
        if (kt + 1 < nkb) {
            load_kv(sb + ((kt + 1) & 1) * ASTAGE * 2, Khi, Klo, Vhi, Vlo,
                    rowbase, headoff, (kt + 1) * 64, tid);
            asm volatile("cp.async.commit_group;" ::: "memory");
            asm volatile("cp.async.wait_group 1;" ::: "memory");
        } else {
            asm volatile("cp.async.wait_group 0;" ::: "memory");
        }
        __syncthreads();

        const int k0 = kt * 64;
        const bool skip = (q0 + w * 16 + 15) < k0;
        if (!skip) {
            const uint32_t base = sb + (kt & 1) * ASTAGE * 2;
            float s[8][4];
#pragma unroll
            for (int t = 0; t < 8; t++)
#pragma unroll
                for (int r = 0; r < 4; r++) s[t][r] = 0.f;

            const int nrow = (lane & 7) + ((lane >> 4) & 1) * 8;
#pragma unroll
            for (int ks = 0; ks < 4; ks++) {
                const int koff = ks * 16 + ((lane >> 3) & 1) * 8;
#pragma unroll
                for (int p = 0; p < 4; p++) {
                    uint32_t kh[4], kl[4];
                    uint32_t ao = (uint32_t)((16 * p + nrow) * ASTRIDE + koff) * 2;
                    ldsm4(kh, base + ao);
                    ldsm4(kl, base + KTILE * 2 + ao);
                    mma16816(s[2 * p],     qh[ks], &kh[0]);
                    mma16816(s[2 * p],     qh[ks], &kl[0]);
                    mma16816(s[2 * p],     ql[ks], &kh[0]);
                    mma16816(s[2 * p + 1], qh[ks], &kh[2]);
                    mma16816(s[2 * p + 1], qh[ks], &kl[2]);
                    mma16816(s[2 * p + 1], ql[ks], &kh[2]);
                }
            }

            const int row0 = q0 + w * 16 + (lane >> 2);
            if (kt >= 2 * qt) {
#pragma unroll
                for (int t = 0; t < 8; t++) {
                    int col = k0 + t * 8 + (lane & 3) * 2;
                    if (col > row0)         s[t][0] = -1e30f;
                    if (col + 1 > row0)     s[t][1] = -1e30f;
                    if (col > row0 + 8)     s[t][2] = -1e30f;
                    if (col + 1 > row0 + 8) s[t][3] = -1e30f;
                }
            }

            float mx0 = -INFINITY, mx1 = -INFINITY;
#pragma unroll
            for (int t = 0; t < 8; t++) {
                mx0 = fmaxf(mx0, fmaxf(s[t][0], s[t][1]));
                mx1 = fmaxf(mx1, fmaxf(s[t][2], s[t][3]));
            }
#pragma unroll
            for (int off = 1; off <= 2; off <<= 1) {
                mx0 = fmaxf(mx0, __shfl_xor_sync(0xffffffffu, mx0, off));
                mx1 = fmaxf(mx1, __shfl_xor_sync(0xffffffffu, mx1, off));
            }
            float mn0 = fmaxf(m0, mx0), mn1 = fmaxf(m1, mx1);
            float al0 = __expf(m0 - mn0), al1 = __expf(m1 - mn1);
            m0 = mn0; m1 = mn1;
            float rs0 = 0.f, rs1 = 0.f;
#pragma unroll
            for (int t = 0; t < 8; t++) {
                s[t][0] = __expf(s[t][0] - mn0);
                s[t][1] = __expf(s[t][1] - mn0);
                s[t][2] = __expf(s[t][2] - mn1);
                s[t][3] = __expf(s[t][3] - mn1);
                rs0 += s[t][0] + s[t][1];
                rs1 += s[t][2] + s[t][3];
            }
#pragma unroll
            for (int off = 1; off <= 2; off <<= 1) {
                rs0 += __shfl_xor_sync(0xffffffffu, rs0, off);
                rs1 += __shfl_xor_sync(0xffffffffu, rs1, off);
            }
            l0 = l0 * al0 + rs0;
            l1 = l1 * al1 + rs1;
#pragma unroll
            for (int t = 0; t < 8; t++) {
                o[t][0] *= al0; o[t][1] *= al0;
                o[t][2] *= al1; o[t][3] *= al1;
            }

            const int vrow0 = lane & 15;
            const int vcoff = (lane >> 4) * 8;
#pragma unroll
            for (int j = 0; j < 4; j++) {
                uint32_t ph[4], pl[4];
                split2(s[2 * j][0], s[2 * j][1], ph[0], pl[0]);
                split2(s[2 * j][2], s[2 * j][3], ph[1], pl[1]);
                split2(s[2 * j + 1][0], s[2 * j + 1][1], ph[2], pl[2]);
                split2(s[2 * j + 1][2], s[2 * j + 1][3], ph[3], pl[3]);
#pragma unroll
                for (int p = 0; p < 4; p++) {
                    uint32_t vh[4], vl[4];
                    uint32_t vo = (uint32_t)((j * 16 + vrow0) * ASTRIDE +
                                             16 * p + vcoff) * 2;
                    ldsm4t(vh, base + 2 * KTILE * 2 + vo);
                    ldsm4t(vl, base + 3 * KTILE * 2 + vo);
                    mma16816(o[2 * p],     ph, &vh[0]);
                    mma16816(o[2 * p],     ph, &vl[0]);
                    mma16816(o[2 * p],     pl, &vh[0]);
                    mma16816(o[2 * p + 1], ph, &vh[2]);
                    mma16816(o[2 * p + 1], ph, &vl[2]);
                    mma16816(o[2 * p + 1], pl, &vh[2]);
                }
            }
        }
        __syncthreads();
    }

    const float inv0 = 1.f / l0, inv1 = 1.f / l1;
    const size_t row = rowbase + q0 + w * 16 + (lane >> 2);
    const size_t col = headoff + (lane & 3) * 2;
#pragma unroll
    for (int t = 0; t < 8; t++) {
        uint32_t h0, l0v, h1, l1v;
        split2(o[t][0] * inv0, o[t][1] * inv0, h0, l0v);
        split2(o[t][2] * inv1, o[t][3] * inv1, h1, l1v);
        *(uint32_t*)&Ohi[row * E_ + col + t * 8] = h0;
        *(uint32_t*)&Olo[row * E_ + col + t * 8] = l0v;
        *(uint32_t*)&Ohi[(row + 8) * E_ + col + t * 8] = h1;
        *(uint32_t*)&Olo[(row + 8) * E_ + col + t * 8] = l1v;
    }
}

// ---------------------------------------------------------------------------
extern "C" void kernel_launch(void* const* d_in, const int* in_sizes, int n_in,
                              void* d_out, int out_size) {
    const float* q_in = (const float*)d_in[0];
    const float* k_in = (const float*)d_in[1];
    const float* v_in = (const float*)d_in[2];
    const float* Wq = (const float*)d_in[3];
    const float* Wk = (const float*)d_in[4];
    const float* Wv = (const float*)d_in[5];
    const float* Wo = (const float*)d_in[6];
    float* out = (float*)d_out;

    float *Q, *K;
    __nv_bfloat16 *Ahi, *Alo, *Thi, *Tlo;
    __nv_bfloat16 *Whi, *Wlo, *W2hi, *W2lo, *W3hi, *W3lo, *W4hi, *W4lo;
    __nv_bfloat16 *Qhi, *Qlo, *Khi, *Klo, *Vhi, *Vlo;
    cudaGetSymbolAddress((void**)&Q, g_Q);
    cudaGetSymbolAddress((void**)&K, g_K);
    cudaGetSymbolAddress((void**)&Ahi, g_Ahi);
    cudaGetSymbolAddress((void**)&Alo, g_Alo);
    cudaGetSymbolAddress((void**)&Thi, g_Thi);
    cudaGetSymbolAddress((void**)&Tlo, g_Tlo);
    cudaGetSymbolAddress((void**)&Whi, g_Whi);
    cudaGetSymbolAddress((void**)&Wlo, g_Wlo);
    cudaGetSymbolAddress((void**)&W2hi, g_W2hi);
    cudaGetSymbolAddress((void**)&W2lo, g_W2lo);
    cudaGetSymbolAddress((void**)&W3hi, g_W3hi);
    cudaGetSymbolAddress((void**)&W3lo, g_W3lo);
    cudaGetSymbolAddress((void**)&W4hi, g_W4hi);
    cudaGetSymbolAddress((void**)&W4lo, g_W4lo);
    cudaGetSymbolAddress((void**)&Qhi, g_Qhi);
    cudaGetSymbolAddress((void**)&Qlo, g_Qlo);
    cudaGetSymbolAddress((void**)&Khi, g_Khi);
    cudaGetSymbolAddress((void**)&Klo, g_Klo);
    cudaGetSymbolAddress((void**)&Vhi, g_Vhi);
    cudaGetSymbolAddress((void**)&Vlo, g_Vlo);

    cudaFuncSetAttribute(gemm_mma, cudaFuncAttributeMaxDynamicSharedMemorySize,
                         GEMM_SMEM);
    cudaFuncSetAttribute(flash_attn_tc,
                         cudaFuncAttributeMaxDynamicSharedMemorySize, ATTN_SMEM);

    const dim3 gg(E_ / 128, MTOT / 128);

    // 0: all weight splits (one launch)
    split_W_all<<<4 * (NW / 4) / 256, 256>>>(Wq, Wk, Wv, Wo);
    // 1: all activation splits (q->Ahi, k->Khi staging, v->Thi)
    split_A_all<<<3 * (NELEM / 4) / 256, 256>>>(q_in, k_in, v_in);
    // 2: Q projection (fp32 out for rope)
    gemm_mma<<<gg, 256, GEMM_SMEM>>>(Ahi, Alo, Whi, Wlo, Q, nullptr, nullptr);
    // 3: K projection (fp32 out for rope; consumes Khi/Klo staging)
    gemm_mma<<<gg, 256, GEMM_SMEM>>>(Khi, Klo, W2hi, W2lo, K, nullptr, nullptr);
    // 4: rope + split (overwrites Qhi/Qlo, Khi/Klo with roped values)
    int rope_threads = 2 * B_ * S_ * H_ * 32;
    rope_split<<<rope_threads / 256, 256>>>(Q, K, Qhi, Qlo, Khi, Klo);
    // 5: V projection -> bf16 hi/lo directly   [ncu window candidate]
    gemm_mma<<<gg, 256, GEMM_SMEM>>>(Thi, Tlo, W3hi, W3lo, nullptr, Vhi, Vlo);
    // 6: attention -> pre-split output in Ahi/Alo   [ncu window candidate]
    flash_attn_tc<<<dim3(S_ / 128, H_, B_), 256, ATTN_SMEM>>>(
        Qhi, Qlo, Khi, Klo, Vhi, Vlo, Ahi, Alo);
    // 7: output projection
    gemm_mma<<<gg, 256, GEMM_SMEM>>>(Ahi, Alo, W4hi, W4lo, out, nullptr, nullptr);
}

// round 9
// speedup vs baseline: 1.1607x; 1.0278x over previous
#include <cuda_runtime.h>
#include <cuda_bf16.h>
#include <math.h>
#include <stdint.h>

#define B_ 4
#define S_ 2048
#define E_ 1024
#define H_ 16
#define D_ 64

static const int MTOT = B_ * S_;          // 8192
#define NELEM (B_ * S_ * E_)              // 8388608
#define NW (E_ * E_)

// ---------------- scratch (__device__ globals; no allocs allowed) ----------
__device__ float g_Q[NELEM];
__device__ float g_K[NELEM];
__device__ __nv_bfloat16 g_Ahi[NELEM];
__device__ __nv_bfloat16 g_Alo[NELEM];
__device__ __nv_bfloat16 g_Thi[NELEM];   // v-projection A staging
__device__ __nv_bfloat16 g_Tlo[NELEM];
__device__ __nv_bfloat16 g_Whi[NW];      // Wq
__device__ __nv_bfloat16 g_Wlo[NW];
__device__ __nv_bfloat16 g_W2hi[NW];     // Wk
__device__ __nv_bfloat16 g_W2lo[NW];
__device__ __nv_bfloat16 g_W3hi[NW];     // Wv
__device__ __nv_bfloat16 g_W3lo[NW];
__device__ __nv_bfloat16 g_W4hi[NW];     // Wo
__device__ __nv_bfloat16 g_W4lo[NW];
__device__ __nv_bfloat16 g_Qhi[NELEM];
__device__ __nv_bfloat16 g_Qlo[NELEM];
__device__ __nv_bfloat16 g_Khi[NELEM];
__device__ __nv_bfloat16 g_Klo[NELEM];
__device__ __nv_bfloat16 g_Vhi[NELEM];
__device__ __nv_bfloat16 g_Vlo[NELEM];
__device__ unsigned int g_ctr[8];        // dynamic tile counters

// ---------------- helpers --------------------------------------------------
__device__ __forceinline__ uint32_t smem_u32(const void* p) {
    uint32_t a;
    asm("{ .reg .u64 t; cvta.to.shared.u64 t, %1; cvt.u32.u64 %0, t; }"
        : "=r"(a) : "l"(p));
    return a;
}
__device__ __forceinline__ void cp16(uint32_t saddr, const void* g) {
    asm volatile("cp.async.cg.shared.global [%0], [%1], 16;"
                 :: "r"(saddr), "l"(g) : "memory");
}
__device__ __forceinline__ void ldsm4(uint32_t* r, uint32_t a) {
    asm volatile("ldmatrix.sync.aligned.m8n8.x4.shared.b16 {%0,%1,%2,%3}, [%4];"
                 : "=r"(r[0]), "=r"(r[1]), "=r"(r[2]), "=r"(r[3]) : "r"(a));
}
__device__ __forceinline__ void ldsm4t(uint32_t* r, uint32_t a) {
    asm volatile("ldmatrix.sync.aligned.m8n8.x4.trans.shared.b16 {%0,%1,%2,%3}, [%4];"
                 : "=r"(r[0]), "=r"(r[1]), "=r"(r[2]), "=r"(r[3]) : "r"(a));
}
__device__ __forceinline__ void mma16816(float* c, const uint32_t* a,
                                         const uint32_t* b) {
    asm volatile(
        "mma.sync.aligned.m16n8k16.row.col.f32.bf16.bf16.f32 "
        "{%0,%1,%2,%3}, {%4,%5,%6,%7}, {%8,%9}, {%0,%1,%2,%3};"
        : "+f"(c[0]), "+f"(c[1]), "+f"(c[2]), "+f"(c[3])
        : "r"(a[0]), "r"(a[1]), "r"(a[2]), "r"(a[3]), "r"(b[0]), "r"(b[1]));
}
__device__ __forceinline__ void split2(float x0, float x1, uint32_t& hi,
                                       uint32_t& lo) {
    __nv_bfloat16 h0 = __float2bfloat16(x0);
    __nv_bfloat16 h1 = __float2bfloat16(x1);
    __nv_bfloat16 l0 = __float2bfloat16(x0 - __bfloat162float(h0));
    __nv_bfloat16 l1 = __float2bfloat16(x1 - __bfloat162float(h1));
    hi = (uint32_t)*(uint16_t*)&h0 | ((uint32_t)*(uint16_t*)&h1 << 16);
    lo = (uint32_t)*(uint16_t*)&l0 | ((uint32_t)*(uint16_t*)&l1 << 16);
}

// ---------------- counter reset -------------------------------------------
__global__ void zero_ctr() {
    if (threadIdx.x < 8) g_ctr[threadIdx.x] = 0;
}

// ---------------- fused split kernels (8 floats / thread, 16B stores) ------
__global__ __launch_bounds__(256)
void split_W_all(const float* __restrict__ W0, const float* __restrict__ W1,
                 const float* __restrict__ W2, const float* __restrict__ W3) {
    int i = blockIdx.x * 256 + threadIdx.x;      // 0 .. 4*2^17-1
    int which = i >> 17;
    int j = i & 0x1FFFF;                          // 8-float chunk index
    const float* src = which == 0 ? W0 : which == 1 ? W1 : which == 2 ? W2 : W3;
    __nv_bfloat16* hi = which == 0 ? g_Whi : which == 1 ? g_W2hi
                       : which == 2 ? g_W3hi : g_W4hi;
    __nv_bfloat16* lo = which == 0 ? g_Wlo : which == 1 ? g_W2lo
                       : which == 2 ? g_W3lo : g_W4lo;
    float4 v0 = ((const float4*)src)[2 * j];
    float4 v1 = ((const float4*)src)[2 * j + 1];
    float f[8] = {v0.x, v0.y, v0.z, v0.w, v1.x, v1.y, v1.z, v1.w};
    uint32_t h[4], l[4];
#pragma unroll
    for (int p = 0; p < 4; p++) split2(f[2 * p], f[2 * p + 1], h[p], l[p]);
    ((uint4*)hi)[j] = make_uint4(h[0], h[1], h[2], h[3]);
    ((uint4*)lo)[j] = make_uint4(l[0], l[1], l[2], l[3]);
}

__global__ __launch_bounds__(256)
void split_A_all(const float* __restrict__ Aq, const float* __restrict__ Ak,
                 const float* __restrict__ Av) {
    int i = blockIdx.x * 256 + threadIdx.x;      // 0 .. 3*2^20-1
    int which = i >> 20;
    int j = i & 0xFFFFF;
    const float* src = which == 0 ? Aq : which == 1 ? Ak : Av;
    __nv_bfloat16* hi = which == 0 ? g_Ahi : which == 1 ? g_Khi : g_Thi;
    __nv_bfloat16* lo = which == 0 ? g_Alo : which == 1 ? g_Klo : g_Tlo;
    float4 v0 = ((const float4*)src)[2 * j];
    float4 v1 = ((const float4*)src)[2 * j + 1];
    float f[8] = {v0.x, v0.y, v0.z, v0.w, v1.x, v1.y, v1.z, v1.w};
    uint32_t h[4], l[4];
#pragma unroll
    for (int p = 0; p < 4; p++) split2(f[2 * p], f[2 * p + 1], h[p], l[p]);
    ((uint4*)hi)[j] = make_uint4(h[0], h[1], h[2], h[3]);
    ((uint4*)lo)[j] = make_uint4(l[0], l[1], l[2], l[3]);
}

// ---------------- GEMM tile body (128x128, BK=32, 8 warps, 2-stage) -------
#define TILEB 10240
#define STAGEB 40960
#define GEMM_SMEM (2 * STAGEB)

__device__ __forceinline__ void load_stage(
    uint32_t sb, int st, const __nv_bfloat16* __restrict__ Ahi,
    const __nv_bfloat16* __restrict__ Alo, const __nv_bfloat16* __restrict__ Bhi,
    const __nv_bfloat16* __restrict__ Blo, int bm, int bn, int k0, int tid) {
    uint32_t s0 = sb + st * STAGEB;
#pragma unroll
    for (int p = 0; p < 2; p++) {
        int chunk = tid + p * 256;
        int row = chunk >> 2;
        int kc = chunk & 3;
        uint32_t soff = (uint32_t)(row * 80 + kc * 16);
        size_t ga = ((size_t)(bm + row) << 10) + k0 + kc * 8;
        size_t gb = ((size_t)(bn + row) << 10) + k0 + kc * 8;
        cp16(s0 + soff,             Ahi + ga);
        cp16(s0 + TILEB + soff,     Alo + ga);
        cp16(s0 + 2 * TILEB + soff, Bhi + gb);
        cp16(s0 + 3 * TILEB + soff, Blo + gb);
    }
}

__device__ __forceinline__ void gemm_tile(
    uint32_t sb, int tid, int lane, int wid,
    const __nv_bfloat16* __restrict__ Ahi, const __nv_bfloat16* __restrict__ Alo,
    const __nv_bfloat16* __restrict__ Whi, const __nv_bfloat16* __restrict__ Wlo,
    float* __restrict__ C, __nv_bfloat16* __restrict__ Chi,
    __nv_bfloat16* __restrict__ Clo, int bm, int bn) {
    const int wm = wid >> 2;
    const int wn = wid & 3;

    float acc[4][4][4];
#pragma unroll
    for (int i = 0; i < 4; i++)
#pragma unroll
        for (int j = 0; j < 4; j++)
#pragma unroll
            for (int r = 0; r < 4; r++) acc[i][j][r] = 0.f;

    load_stage(sb, 0, Ahi, Alo, Whi, Wlo, bm, bn, 0, tid);
    asm volatile("cp.async.commit_group;" ::: "memory");

    const int NCH = E_ / 32;   // 32
    for (int c = 0; c < NCH; c++) {
        if (c + 1 < NCH) {
            load_stage(sb, (c + 1) & 1, Ahi, Alo, Whi, Wlo, bm, bn,
                       (c + 1) * 32, tid);
            asm volatile("cp.async.commit_group;" ::: "memory");
            asm volatile("cp.async.wait_group 1;" ::: "memory");
        } else {
            asm volatile("cp.async.wait_group 0;" ::: "memory");
        }
        __syncthreads();

        const uint32_t s0 = sb + (c & 1) * STAGEB;
        const uint32_t sAh = s0, sAl = s0 + TILEB;
        const uint32_t sBh = s0 + 2 * TILEB, sBl = s0 + 3 * TILEB;

#pragma unroll
        for (int ks = 0; ks < 32; ks += 16) {
            uint32_t bhi[2][4], blo[2][4];
            const int brow = wn * 32 + (lane & 7) + ((lane >> 4) & 1) * 8;
            const int bkk = ks + ((lane >> 3) & 1) * 8;
#pragma unroll
            for (int nb = 0; nb < 2; nb++) {
                uint32_t bo = (uint32_t)((brow + nb * 16) * 80 + bkk * 2);
                ldsm4(bhi[nb], sBh + bo);
                ldsm4(blo[nb], sBl + bo);
            }
            const int arow = wm * 64 + (lane & 7) + ((lane >> 3) & 1) * 8;
            const int akk = ks + (lane >> 4) * 8;
#pragma unroll
            for (int mi = 0; mi < 4; mi++) {
                uint32_t ahi[4], alo[4];
                uint32_t ao = (uint32_t)((arow + mi * 16) * 80 + akk * 2);
                ldsm4(ahi, sAh + ao);
                ldsm4(alo, sAl + ao);
#pragma unroll
                for (int ni = 0; ni < 4; ni++)
                    mma16816(acc[mi][ni], ahi, &bhi[ni >> 1][(ni & 1) * 2]);
#pragma unroll
                for (int ni = 0; ni < 4; ni++)
                    mma16816(acc[mi][ni], ahi, &blo[ni >> 1][(ni & 1) * 2]);
#pragma unroll
                for (int ni = 0; ni < 4; ni++)
                    mma16816(acc[mi][ni], alo, &bhi[ni >> 1][(ni & 1) * 2]);
            }
        }
        __syncthreads();
    }

    const int r0 = bm + wm * 64 + (lane >> 2);
    const int c0 = bn + wn * 32 + (lane & 3) * 2;
    if (C) {
#pragma unroll
        for (int mi = 0; mi < 4; mi++)
#pragma unroll
            for (int ni = 0; ni < 4; ni++) {
                int row = r0 + mi * 16;
                int col = c0 + ni * 8;
                *(float2*)&C[(size_t)row * E_ + col] =
                    make_float2(acc[mi][ni][0], acc[mi][ni][1]);
                *(float2*)&C[(size_t)(row + 8) * E_ + col] =
                    make_float2(acc[mi][ni][2], acc[mi][ni][3]);
            }
    } else {
#pragma unroll
        for (int mi = 0; mi < 4; mi++)
#pragma unroll
            for (int ni = 0; ni < 4; ni++) {
                int row = r0 + mi * 16;
                int col = c0 + ni * 8;
                uint32_t h0, l0v, h1, l1v;
                split2(acc[mi][ni][0], acc[mi][ni][1], h0, l0v);
                split2(acc[mi][ni][2], acc[mi][ni][3], h1, l1v);
                *(uint32_t*)&Chi[(size_t)row * E_ + col] = h0;
                *(uint32_t*)&Clo[(size_t)row * E_ + col] = l0v;
                *(uint32_t*)&Chi[(size_t)(row + 8) * E_ + col] = h1;
                *(uint32_t*)&Clo[(size_t)(row + 8) * E_ + col] = l1v;
            }
    }
}

// Persistent fused Q/K/V projection: 1536 tiles pooled on g_ctr[0].
__global__ __launch_bounds__(256, 2)
void gemm_qkv() {
    extern __shared__ char smem[];
    const uint32_t sb = smem_u32(smem);
    const int tid = threadIdx.x;
    const int lane = tid & 31;
    const int wid = tid >> 5;
    __shared__ unsigned s_t;

    for (;;) {
        if (tid == 0) s_t = atomicAdd(&g_ctr[0], 1u);
        __syncthreads();
        unsigned t = s_t;
        __syncthreads();
        if (t >= 1536u) return;
        int which = t >> 9;
        int rem = t & 511;
        int bm = (rem >> 3) * 128, bn = (rem & 7) * 128;
        if (which == 0)
            gemm_tile(sb, tid, lane, wid, g_Ahi, g_Alo, g_Whi, g_Wlo,
                      g_Q, nullptr, nullptr, bm, bn);
        else if (which == 1)
            gemm_tile(sb, tid, lane, wid, g_Khi, g_Klo, g_W2hi, g_W2lo,
                      g_K, nullptr, nullptr, bm, bn);
        else
            gemm_tile(sb, tid, lane, wid, g_Thi, g_Tlo, g_W3hi, g_W3lo,
                      nullptr, g_Vhi, g_Vlo, bm, bn);
    }
}

// Persistent output projection: 512 tiles on g_ctr[1].
__global__ __launch_bounds__(256, 2)
void gemm_o(float* __restrict__ out) {
    extern __shared__ char smem[];
    const uint32_t sb = smem_u32(smem);
    const int tid = threadIdx.x;
    const int lane = tid & 31;
    const int wid = tid >> 5;
    __shared__ unsigned s_t;

    for (;;) {
        if (tid == 0) s_t = atomicAdd(&g_ctr[1], 1u);
        __syncthreads();
        unsigned t = s_t;
        __syncthreads();
        if (t >= 512u) return;
        int bm = (t >> 3) * 128, bn = (t & 7) * 128;
        gemm_tile(sb, tid, lane, wid, g_Ahi, g_Alo, g_W4hi, g_W4lo,
                  out, nullptr, nullptr, bm, bn);
    }
}

// ---------------- RoPE + bf16 split. Q gets 1/8 scale folded in. ----------
__global__ void rope_split(const float* __restrict__ Q, const float* __restrict__ K,
                           __nv_bfloat16* __restrict__ Qhi, __nv_bfloat16* __restrict__ Qlo,
                           __nv_bfloat16* __restrict__ Khi, __nv_bfloat16* __restrict__ Klo) {
    const int per = B_ * S_ * H_ * 32;
    int idx = blockIdx.x * blockDim.x + threadIdx.x;
    if (idx >= 2 * per) return;
    bool isQ = idx < per;
    int r = isQ ? idx : idx - per;
    int i = r & 31;
    int hh = (r >> 5) & (H_ - 1);
    int s = (r >> 9) & (S_ - 1);
    int b = r >> 20;

    float inv_freq = __expf(-(float)i * (logf(10000.0f) / 32.0f));
    float ang = (float)s * inv_freq;
    float sn, cs;
    sincosf(ang, &sn, &cs);

    size_t base = ((size_t)(b * S_ + s)) * E_ + hh * D_ + i;
    const float* src = isQ ? Q : K;
    float x1 = src[base];
    float x2 = src[base + 32];
    float y1 = x1 * cs - x2 * sn;
    float y2 = x2 * cs + x1 * sn;
    if (isQ) { y1 *= 0.125f; y2 *= 0.125f; }

    __nv_bfloat16* hi = isQ ? Qhi : Khi;
    __nv_bfloat16* lo = isQ ? Qlo : Klo;
    __nv_bfloat16 h1 = __float2bfloat16(y1);
    __nv_bfloat16 h2 = __float2bfloat16(y2);
    hi[base] = h1;
    hi[base + 32] = h2;
    lo[base] = __float2bfloat16(y1 - __bfloat162float(h1));
    lo[base + 32] = __float2bfloat16(y2 - __bfloat162float(h2));
}

// ---------------- tensor-core causal flash attention ----------------------
#define ASTRIDE 72
#define KTILE (64 * ASTRIDE)
#define ASTAGE (4 * KTILE)
#define ATTN_SMEM (2 * ASTAGE * 2)

__device__ __forceinline__ void load_kv(
    uint32_t sb, const __nv_bfloat16* __restrict__ Khi,
    const __nv_bfloat16* __restrict__ Klo, const __nv_bfloat16* __restrict__ Vhi,
    const __nv_bfloat16* __restrict__ Vlo, size_t rowbase, size_t headoff,
    int k0, int tid) {
#pragma unroll
    for (int p = 0; p < 2; p++) {
        int chunk = tid + p * 256;
        int row = chunk >> 3;
        int c8 = chunk & 7;
        size_t g = (rowbase + k0 + row) * E_ + headoff + c8 * 8;
        uint32_t so = (uint32_t)(row * ASTRIDE + c8 * 8) * 2;
        cp16(sb + so,                 Khi + g);
        cp16(sb + KTILE * 2 + so,     Klo + g);
        cp16(sb + 2 * KTILE * 2 + so, Vhi + g);
        cp16(sb + 3 * KTILE * 2 + so, Vlo + g);
    }
}

__global__ __launch_bounds__(256, 2)
void flash_attn_tc(const __nv_bfloat16* __restrict__ Qhi,
                   const __nv_bfloat16* __restrict__ Qlo,
                   const __nv_bfloat16* __restrict__ Khi,
                   const __nv_bfloat16* __restrict__ Klo,
                   const __nv_bfloat16* __restrict__ Vhi,
                   const __nv_bfloat16* __restrict__ Vlo,
                   __nv_bfloat16* __restrict__ Ohi,
                   __nv_bfloat16* __restrict__ Olo) {
    extern __shared__ char smem[];
    const uint32_t sb = smem_u32(smem);
    const int tid = threadIdx.x;
    const int lane = tid & 31;
    const int w = tid >> 5;
    const int qt = gridDim.x - 1 - blockIdx.x;
    const int h = blockIdx.y;
    const int b = blockIdx.z;
    const int q0 = qt * 128;
    const size_t rowbase = (size_t)(b * S_);
    const size_t headoff = (size_t)h * D_;

#pragma unroll
    for (int p = 0; p < 4; p++) {
        int chunk = tid + p * 256;
        int row = chunk >> 3;
        int c8 = chunk & 7;
        size_t g = (rowbase + q0 + row) * E_ + headoff + c8 * 8;
        uint32_t so = (uint32_t)(row * ASTRIDE + c8 * 8) * 2;
        cp16(sb + so, Qhi + g);
        cp16(sb + 2 * KTILE * 2 + so, Qlo + g);
    }
    asm volatile("cp.async.commit_group;" ::: "memory");
    asm volatile("cp.async.wait_group 0;" ::: "memory");
    __syncthreads();

    uint32_t qh[4][4], ql[4][4];
    {
        const int arow = w * 16 + (lane & 7) + ((lane >> 3) & 1) * 8;
#pragma unroll
        for (int ks = 0; ks < 4; ks++) {
            const int koff = ks * 16 + (lane >> 4) * 8;
            uint32_t ao = (uint32_t)(arow * ASTRIDE + koff) * 2;
            ldsm4(qh[ks], sb + ao);
            ldsm4(ql[ks], sb + 2 * KTILE * 2 + ao);
        }
    }
    __syncthreads();

    float m0 = -INFINITY, m1 = -INFINITY, l0 = 0.f, l1 = 0.f;
    float o[8][4];
#pragma unroll
    for (int t = 0; t < 8; t++)
#pragma unroll
        for (int r = 0; r < 4; r++) o[t][r] = 0.f;

    const int nkb = 2 * (qt + 1);
    load_kv(sb, Khi, Klo, Vhi, Vlo, rowbase, headoff, 0, tid);
    asm volatile("cp.async.commit_group;" ::: "memory");

    for (int kt = 0; kt < nkb; kt++) {
        if (kt + 1 < nkb) {
            load_kv(sb + ((kt + 1) & 1) * ASTAGE * 2, Khi, Klo, Vhi, Vlo,
                    rowbase, headoff, (kt + 1) * 64, tid);
            asm volatile("cp.async.commit_group;" ::: "memory");
            asm volatile("cp.async.wait_group 1;" ::: "memory");
        } else {
            asm volatile("cp.async.wait_group 0;" ::: "memory");
        }
        __syncthreads();

        const int k0 = kt * 64;
        const bool skip = (q0 + w * 16 + 15) < k0;
        if (!skip) {
            const uint32_t base = sb + (kt & 1) * ASTAGE * 2;
            float s[8][4];
#pragma unroll
            for (int t = 0; t < 8; t++)
#pragma unroll
                for (int r = 0; r < 4; r++) s[t][r] = 0.f;

            const int nrow = (lane & 7) + ((lane >> 4) & 1) * 8;
#pragma unroll
            for (int ks = 0; ks < 4; ks++) {
                const int koff = ks * 16 + ((lane >> 3) & 1) * 8;
#pragma unroll
                for (int p = 0; p < 4; p++) {
                    uint32_t kh[4], kl[4];
                    uint32_t ao = (uint32_t)((16 * p + nrow) * ASTRIDE + koff) * 2;
                    ldsm4(kh, base + ao);
                    ldsm4(kl, base + KTILE * 2 + ao);
                    mma16816(s[2 * p],     qh[ks], &kh[0]);
                    mma16816(s[2 * p],     qh[ks], &kl[0]);
                    mma16816(s[2 * p],     ql[ks], &kh[0]);
                    mma16816(s[2 * p + 1], qh[ks], &kh[2]);
                    mma16816(s[2 * p + 1], qh[ks], &kl[2]);
                    mma16816(s[2 * p + 1], ql[ks], &kh[2]);
                }
            }

            const int row0 = q0 + w * 16 + (lane >> 2);
            if (kt >= 2 * qt) {
#pragma unroll
                for (int t = 0; t < 8; t++) {
                    int col = k0 + t * 8 + (lane & 3) * 2;
                    if (col > row0)         s[t][0] = -1e30f;
                    if (col + 1 > row0)     s[t][1] = -1e30f;
                    if (col > row0 + 8)     s[t][2] = -1e30f;
                    if (col + 1 > row0 + 8) s[t][3] = -1e30f;
                }
            }

            float mx0 = -INFINITY, mx1 = -INFINITY;
#pragma unroll
            for (int t = 0; t < 8; t++) {
                mx0 = fmaxf(mx0, fmaxf(s[t][0], s[t][1]));
                mx1 = fmaxf(mx1, fmaxf(s[t][2], s[t][3]));
            }
#pragma unroll
            for (int off = 1; off <= 2; off <<= 1) {
                mx0 = fmaxf(mx0, __shfl_xor_sync(0xffffffffu, mx0, off));
                mx1 = fmaxf(mx1, __shfl_xor_sync(0xffffffffu, mx1, off));
            }
            float mn0 = fmaxf(m0, mx0), mn1 = fmaxf(m1, mx1);
            float al0 = __expf(m0 - mn0), al1 = __expf(m1 - mn1);
            m0 = mn0; m1 = mn1;
            float rs0 = 0.f, rs1 = 0.f;
#pragma unroll
            for (int t = 0; t < 8; t++) {
                s[t][0] = __expf(s[t][0] - mn0);
                s[t][1] = __expf(s[t][1] - mn0);
                s[t][2] = __expf(s[t][2] - mn1);
                s[t][3] = __expf(s[t][3] - mn1);
                rs0 += s[t][0] + s[t][1];
                rs1 += s[t][2] + s[t][3];
            }
#pragma unroll
            for (int off = 1; off <= 2; off <<= 1) {
                rs0 += __shfl_xor_sync(0xffffffffu, rs0, off);
                rs1 += __shfl_xor_sync(0xffffffffu, rs1, off);
            }
            l0 = l0 * al0 + rs0;
            l1 = l1 * al1 + rs1;
#pragma unroll
            for (int t = 0; t < 8; t++) {
                o[t][0] *= al0; o[t][1] *= al0;
                o[t][2] *= al1; o[t][3] *= al1;
            }

            const int vrow0 = lane & 15;
            const int vcoff = (lane >> 4) * 8;
#pragma unroll
            for (int j = 0; j < 4; j++) {
                uint32_t ph[4], pl[4];
                split2(s[2 * j][0], s[2 * j][1], ph[0], pl[0]);
                split2(s[2 * j][2], s[2 * j][3], ph[1], pl[1]);
                split2(s[2 * j + 1][0], s[2 * j + 1][1], ph[2], pl[2]);
                split2(s[2 * j + 1][2], s[2 * j + 1][3], ph[3], pl[3]);
#pragma unroll
                for (int p = 0; p < 4; p++) {
                    uint32_t vh[4], vl[4];
                    uint32_t vo = (uint32_t)((j * 16 + vrow0) * ASTRIDE +
                                             16 * p + vcoff) * 2;
                    ldsm4t(vh, base + 2 * KTILE * 2 + vo);
                    ldsm4t(vl, base + 3 * KTILE * 2 + vo);
                    mma16816(o[2 * p],     ph, &vh[0]);
                    mma16816(o[2 * p],     ph, &vl[0]);
                    mma16816(o[2 * p],     pl, &vh[0]);
                    mma16816(o[2 * p + 1], ph, &vh[2]);
                    mma16816(o[2 * p + 1], ph, &vl[2]);
                    mma16816(o[2 * p + 1], pl, &vh[2]);
                }
            }
        }
        __syncthreads();
    }

    const float inv0 = 1.f / l0, inv1 = 1.f / l1;
    const size_t row = rowbase + q0 + w * 16 + (lane >> 2);
    const size_t col = headoff + (lane & 3) * 2;
#pragma unroll
    for (int t = 0; t < 8; t++) {
        uint32_t h0, l0v, h1, l1v;
        split2(o[t][0] * inv0, o[t][1] * inv0, h0, l0v);
        split2(o[t][2] * inv1, o[t][3] * inv1, h1, l1v);
        *(uint32_t*)&Ohi[row * E_ + col + t * 8] = h0;
        *(uint32_t*)&Olo[row * E_ + col + t * 8] = l0v;
        *(uint32_t*)&Ohi[(row + 8) * E_ + col + t * 8] = h1;
        *(uint32_t*)&Olo[(row + 8) * E_ + col + t * 8] = l1v;
    }
}

// ---------------------------------------------------------------------------
extern "C" void kernel_launch(void* const* d_in, const int* in_sizes, int n_in,
                              void* d_out, int out_size) {
    const float* q_in = (const float*)d_in[0];
    const float* k_in = (const float*)d_in[1];
    const float* v_in = (const float*)d_in[2];
    const float* Wq = (const float*)d_in[3];
    const float* Wk = (const float*)d_in[4];
    const float* Wv = (const float*)d_in[5];
    const float* Wo = (const float*)d_in[6];
    float* out = (float*)d_out;

    float *Q, *K;
    __nv_bfloat16 *Qhi, *Qlo, *Khi, *Klo, *Vhi, *Vlo, *Ahi, *Alo;
    cudaGetSymbolAddress((void**)&Q, g_Q);
    cudaGetSymbolAddress((void**)&K, g_K);
    cudaGetSymbolAddress((void**)&Qhi, g_Qhi);
    cudaGetSymbolAddress((void**)&Qlo, g_Qlo);
    cudaGetSymbolAddress((void**)&Khi, g_Khi);
    cudaGetSymbolAddress((void**)&Klo, g_Klo);
    cudaGetSymbolAddress((void**)&Vhi, g_Vhi);
    cudaGetSymbolAddress((void**)&Vlo, g_Vlo);
    cudaGetSymbolAddress((void**)&Ahi, g_Ahi);
    cudaGetSymbolAddress((void**)&Alo, g_Alo);

    cudaFuncSetAttribute(gemm_qkv, cudaFuncAttributeMaxDynamicSharedMemorySize,
                         GEMM_SMEM);
    cudaFuncSetAttribute(gemm_o, cudaFuncAttributeMaxDynamicSharedMemorySize,
                         GEMM_SMEM);
    cudaFuncSetAttribute(flash_attn_tc,
                         cudaFuncAttributeMaxDynamicSharedMemorySize, ATTN_SMEM);

    // 0: reset dynamic-tile counters
    zero_ctr<<<1, 32>>>();
    // 1: weight splits (one launch, 16B stores)
    split_W_all<<<4 * (NW / 8) / 256, 256>>>(Wq, Wk, Wv, Wo);
    // 2: activation splits (q->Ahi, k->Khi staging, v->Thi)
    split_A_all<<<3 * (NELEM / 8) / 256, 256>>>(q_in, k_in, v_in);
    // 3: fused persistent Q/K/V projections (dynamic 1536-tile pool)
    gemm_qkv<<<304, 256, GEMM_SMEM>>>();
    // 4: rope + split (overwrites Qhi/Qlo, Khi/Klo with roped values)
    int rope_threads = 2 * B_ * S_ * H_ * 32;
    rope_split<<<rope_threads / 256, 256>>>(Q, K, Qhi, Qlo, Khi, Klo);
    // 5: attention -> pre-split output in Ahi/Alo
    flash_attn_tc<<<dim3(S_ / 128, H_, B_), 256, ATTN_SMEM>>>(
        Qhi, Qlo, Khi, Klo, Vhi, Vlo, Ahi, Alo);
    // 6: persistent output projection (dynamic 512-tile pool)
    gemm_o<<<304, 256, GEMM_SMEM>>>(out);
}

// round 10
// speedup vs baseline: 1.7376x; 1.4970x over previous
#include <cuda_runtime.h>
#include <cuda_fp16.h>
#include <math.h>
#include <stdint.h>

#define B_ 4
#define S_ 2048
#define E_ 1024
#define H_ 16
#define D_ 64

static const int MTOT = B_ * S_;          // 8192
#define NELEM (B_ * S_ * E_)              // 8388608
#define NW (E_ * E_)

// ---------------- scratch (__device__ globals; no allocs allowed) ----------
__device__ float g_Q[NELEM];
__device__ float g_K[NELEM];
__device__ __half g_hA[NELEM];    // q-activation staging; later attention output
__device__ __half g_hKs[NELEM];   // k-activation staging (single)
__device__ __half g_hT[NELEM];    // v-activation staging (single)
__device__ __half g_W1h[NW], g_W1l[NW];
__device__ __half g_W2h[NW], g_W2l[NW];
__device__ __half g_W3h[NW], g_W3l[NW];
__device__ __half g_W4h[NW], g_W4l[NW];
__device__ __half g_Qh[NELEM];                 // roped Q (single, 1/8 folded)
__device__ __half g_Kh[NELEM], g_Kl[NELEM];    // roped K hi/lo
__device__ __half g_Vh[NELEM], g_Vl[NELEM];    // V hi/lo
__device__ unsigned int g_ctr[8];

// ---------------- helpers --------------------------------------------------
__device__ __forceinline__ uint32_t smem_u32(const void* p) {
    uint32_t a;
    asm("{ .reg .u64 t; cvta.to.shared.u64 t, %1; cvt.u32.u64 %0, t; }"
        : "=r"(a) : "l"(p));
    return a;
}
__device__ __forceinline__ void cp16(uint32_t saddr, const void* g) {
    asm volatile("cp.async.cg.shared.global [%0], [%1], 16;"
                 :: "r"(saddr), "l"(g) : "memory");
}
__device__ __forceinline__ void ldsm4(uint32_t* r, uint32_t a) {
    asm volatile("ldmatrix.sync.aligned.m8n8.x4.shared.b16 {%0,%1,%2,%3}, [%4];"
                 : "=r"(r[0]), "=r"(r[1]), "=r"(r[2]), "=r"(r[3]) : "r"(a));
}
__device__ __forceinline__ void ldsm4t(uint32_t* r, uint32_t a) {
    asm volatile("ldmatrix.sync.aligned.m8n8.x4.trans.shared.b16 {%0,%1,%2,%3}, [%4];"
                 : "=r"(r[0]), "=r"(r[1]), "=r"(r[2]), "=r"(r[3]) : "r"(a));
}
__device__ __forceinline__ void mma16816(float* c, const uint32_t* a,
                                         const uint32_t* b) {
    asm volatile(
        "mma.sync.aligned.m16n8k16.row.col.f32.f16.f16.f32 "
        "{%0,%1,%2,%3}, {%4,%5,%6,%7}, {%8,%9}, {%0,%1,%2,%3};"
        : "+f"(c[0]), "+f"(c[1]), "+f"(c[2]), "+f"(c[3])
        : "r"(a[0]), "r"(a[1]), "r"(a[2]), "r"(a[3]), "r"(b[0]), "r"(b[1]));
}
__device__ __forceinline__ uint32_t pack2h(float x0, float x1) {
    __half2 h = __floats2half2_rn(x0, x1);
    return *(uint32_t*)&h;
}
__device__ __forceinline__ void split2h(float x0, float x1, uint32_t& hi,
                                        uint32_t& lo) {
    __half h0 = __float2half_rn(x0);
    __half h1 = __float2half_rn(x1);
    __half l0 = __float2half_rn(x0 - __half2float(h0));
    __half l1 = __float2half_rn(x1 - __half2float(h1));
    hi = (uint32_t)*(uint16_t*)&h0 | ((uint32_t)*(uint16_t*)&h1 << 16);
    lo = (uint32_t)*(uint16_t*)&l0 | ((uint32_t)*(uint16_t*)&l1 << 16);
}

// ---------------- counter reset -------------------------------------------
__global__ void zero_ctr() {
    if (threadIdx.x < 8) g_ctr[threadIdx.x] = 0;
}

// ---------------- weight split (fp16 hi/lo), all four in one launch --------
__global__ __launch_bounds__(256)
void split_W_all(const float* __restrict__ W0, const float* __restrict__ W1,
                 const float* __restrict__ W2, const float* __restrict__ W3) {
    int i = blockIdx.x * 256 + threadIdx.x;      // 4 * 2^17
    int which = i >> 17;
    int j = i & 0x1FFFF;
    const float* src = which == 0 ? W0 : which == 1 ? W1 : which == 2 ? W2 : W3;
    __half* hi = which == 0 ? g_W1h : which == 1 ? g_W2h
                : which == 2 ? g_W3h : g_W4h;
    __half* lo = which == 0 ? g_W1l : which == 1 ? g_W2l
                : which == 2 ? g_W3l : g_W4l;
    float4 v0 = ((const float4*)src)[2 * j];
    float4 v1 = ((const float4*)src)[2 * j + 1];
    float f[8] = {v0.x, v0.y, v0.z, v0.w, v1.x, v1.y, v1.z, v1.w};
    uint32_t h[4], l[4];
#pragma unroll
    for (int p = 0; p < 4; p++) split2h(f[2 * p], f[2 * p + 1], h[p], l[p]);
    ((uint4*)hi)[j] = make_uint4(h[0], h[1], h[2], h[3]);
    ((uint4*)lo)[j] = make_uint4(l[0], l[1], l[2], l[3]);
}

// ---------------- activation convert (fp16 single), q/k/v in one launch ----
__global__ __launch_bounds__(256)
void conv_A_all(const float* __restrict__ Aq, const float* __restrict__ Ak,
                const float* __restrict__ Av) {
    int i = blockIdx.x * 256 + threadIdx.x;      // 3 * 2^20
    int which = i >> 20;
    int j = i & 0xFFFFF;
    const float* src = which == 0 ? Aq : which == 1 ? Ak : Av;
    __half* dst = which == 0 ? g_hA : which == 1 ? g_hKs : g_hT;
    float4 v0 = ((const float4*)src)[2 * j];
    float4 v1 = ((const float4*)src)[2 * j + 1];
    float f[8] = {v0.x, v0.y, v0.z, v0.w, v1.x, v1.y, v1.z, v1.w};
    uint32_t h[4];
#pragma unroll
    for (int p = 0; p < 4; p++) h[p] = pack2h(f[2 * p], f[2 * p + 1]);
    ((uint4*)dst)[j] = make_uint4(h[0], h[1], h[2], h[3]);
}

// ---------------- GEMM tile body (128x128, BK=64, 8 warps, 2-stage) -------
// Stage = {A (single), Bh, Bl}: 3 tiles x 128 rows x 144B = 55296 B.
// Single __syncthreads per chunk; 16 chunks.
#define ROWB 144
#define TILEH (128 * ROWB)                 // 18432
#define STAGEH (3 * TILEH)                 // 55296
#define GEMM_SMEM (2 * STAGEH)             // 110592

__device__ __forceinline__ void load_stage3(
    uint32_t sb, int st, const __half* __restrict__ A,
    const __half* __restrict__ Bh, const __half* __restrict__ Bl,
    int bm, int bn, int k0, int tid) {
    uint32_t s0 = sb + st * STAGEH;
#pragma unroll
    for (int p = 0; p < 4; p++) {
        int chunk = tid + p * 256;          // 0..1023
        int row = chunk >> 3;               // 0..127
        int c16 = chunk & 7;                // 16B unit (8 halves)
        uint32_t soff = (uint32_t)(row * ROWB + c16 * 16);
        size_t ga = ((size_t)(bm + row) << 10) + k0 + c16 * 8;
        size_t gb = ((size_t)(bn + row) << 10) + k0 + c16 * 8;
        cp16(s0 + soff,             A + ga);
        cp16(s0 + TILEH + soff,     Bh + gb);
        cp16(s0 + 2 * TILEH + soff, Bl + gb);
    }
}

__device__ __forceinline__ void gemm_tile(
    uint32_t sb, int tid, int lane, int wid,
    const __half* __restrict__ A, const __half* __restrict__ Bh,
    const __half* __restrict__ Bl, float* __restrict__ C,
    __half* __restrict__ Chi, __half* __restrict__ Clo, int bm, int bn) {
    const int wm = wid >> 2;
    const int wn = wid & 3;

    float acc[4][4][4];
#pragma unroll
    for (int i = 0; i < 4; i++)
#pragma unroll
        for (int j = 0; j < 4; j++)
#pragma unroll
            for (int r = 0; r < 4; r++) acc[i][j][r] = 0.f;

    load_stage3(sb, 0, A, Bh, Bl, bm, bn, 0, tid);
    asm volatile("cp.async.commit_group;" ::: "memory");

    const int NCH = E_ / 64;   // 16
    for (int c = 0; c < NCH; c++) {
        asm volatile("cp.async.wait_group 0;" ::: "memory");
        __syncthreads();
        if (c + 1 < NCH) {
            load_stage3(sb, (c + 1) & 1, A, Bh, Bl, bm, bn, (c + 1) * 64, tid);
            asm volatile("cp.async.commit_group;" ::: "memory");
        }

        const uint32_t s0 = sb + (c & 1) * STAGEH;
        const uint32_t sA = s0, sBh = s0 + TILEH, sBl = s0 + 2 * TILEH;

#pragma unroll
        for (int ks = 0; ks < 64; ks += 16) {
            uint32_t bhi[2][4], blo[2][4];
            const int brow = wn * 32 + (lane & 7) + ((lane >> 4) & 1) * 8;
            const int bkk = ks + ((lane >> 3) & 1) * 8;
#pragma unroll
            for (int nb = 0; nb < 2; nb++) {
                uint32_t bo = (uint32_t)((brow + nb * 16) * ROWB + bkk * 2);
                ldsm4(bhi[nb], sBh + bo);
                ldsm4(blo[nb], sBl + bo);
            }
            const int arow = wm * 64 + (lane & 7) + ((lane >> 3) & 1) * 8;
            const int akk = ks + (lane >> 4) * 8;
#pragma unroll
            for (int mi = 0; mi < 4; mi++) {
                uint32_t a[4];
                uint32_t ao = (uint32_t)((arow + mi * 16) * ROWB + akk * 2);
                ldsm4(a, sA + ao);
#pragma unroll
                for (int ni = 0; ni < 4; ni++)
                    mma16816(acc[mi][ni], a, &bhi[ni >> 1][(ni & 1) * 2]);
#pragma unroll
                for (int ni = 0; ni < 4; ni++)
                    mma16816(acc[mi][ni], a, &blo[ni >> 1][(ni & 1) * 2]);
            }
        }
    }
    __syncthreads();   // protect stage 0 vs next tile's prologue load

    const int r0 = bm + wm * 64 + (lane >> 2);
    const int c0 = bn + wn * 32 + (lane & 3) * 2;
    if (C) {
#pragma unroll
        for (int mi = 0; mi < 4; mi++)
#pragma unroll
            for (int ni = 0; ni < 4; ni++) {
                int row = r0 + mi * 16;
                int col = c0 + ni * 8;
                *(float2*)&C[(size_t)row * E_ + col] =
                    make_float2(acc[mi][ni][0], acc[mi][ni][1]);
                *(float2*)&C[(size_t)(row + 8) * E_ + col] =
                    make_float2(acc[mi][ni][2], acc[mi][ni][3]);
            }
    } else {
#pragma unroll
        for (int mi = 0; mi < 4; mi++)
#pragma unroll
            for (int ni = 0; ni < 4; ni++) {
                int row = r0 + mi * 16;
                int col = c0 + ni * 8;
                uint32_t h0, l0v, h1, l1v;
                split2h(acc[mi][ni][0], acc[mi][ni][1], h0, l0v);
                split2h(acc[mi][ni][2], acc[mi][ni][3], h1, l1v);
                *(uint32_t*)&Chi[(size_t)row * E_ + col] = h0;
                *(uint32_t*)&Clo[(size_t)row * E_ + col] = l0v;
                *(uint32_t*)&Chi[(size_t)(row + 8) * E_ + col] = h1;
                *(uint32_t*)&Clo[(size_t)(row + 8) * E_ + col] = l1v;
            }
    }
}

// Persistent fused Q/K/V projections: 1536 tiles on g_ctr[0].
__global__ __launch_bounds__(256, 2)
void gemm_qkv() {
    extern __shared__ char smem[];
    const uint32_t sb = smem_u32(smem);
    const int tid = threadIdx.x;
    const int lane = tid & 31;
    const int wid = tid >> 5;
    __shared__ unsigned s_t;

    for (;;) {
        if (tid == 0) s_t = atomicAdd(&g_ctr[0], 1u);
        __syncthreads();
        unsigned t = s_t;
        __syncthreads();
        if (t >= 1536u) return;
        int which = t >> 9;
        int rem = t & 511;
        int bm = (rem >> 3) * 128, bn = (rem & 7) * 128;
        if (which == 0)
            gemm_tile(sb, tid, lane, wid, g_hA, g_W1h, g_W1l,
                      g_Q, nullptr, nullptr, bm, bn);
        else if (which == 1)
            gemm_tile(sb, tid, lane, wid, g_hKs, g_W2h, g_W2l,
                      g_K, nullptr, nullptr, bm, bn);
        else
            gemm_tile(sb, tid, lane, wid, g_hT, g_W3h, g_W3l,
                      nullptr, g_Vh, g_Vl, bm, bn);
    }
}

// Persistent output projection: 512 tiles on g_ctr[1].
__global__ __launch_bounds__(256, 2)
void gemm_o(float* __restrict__ out) {
    extern __shared__ char smem[];
    const uint32_t sb = smem_u32(smem);
    const int tid = threadIdx.x;
    const int lane = tid & 31;
    const int wid = tid >> 5;
    __shared__ unsigned s_t;

    for (;;) {
        if (tid == 0) s_t = atomicAdd(&g_ctr[1], 1u);
        __syncthreads();
        unsigned t = s_t;
        __syncthreads();
        if (t >= 512u) return;
        int bm = (t >> 3) * 128, bn = (t & 7) * 128;
        gemm_tile(sb, tid, lane, wid, g_hA, g_W4h, g_W4l,
                  out, nullptr, nullptr, bm, bn);
    }
}

// ---------------- RoPE: Q -> single fp16 (1/8 folded), K -> fp16 hi/lo ----
__global__ void rope_split(const float* __restrict__ Q, const float* __restrict__ K) {
    const int per = B_ * S_ * H_ * 32;
    int idx = blockIdx.x * blockDim.x + threadIdx.x;
    if (idx >= 2 * per) return;
    bool isQ = idx < per;
    int r = isQ ? idx : idx - per;
    int i = r & 31;
    int hh = (r >> 5) & (H_ - 1);
    int s = (r >> 9) & (S_ - 1);
    int b = r >> 20;

    float inv_freq = __expf(-(float)i * (logf(10000.0f) / 32.0f));
    float ang = (float)s * inv_freq;
    float sn, cs;
    sincosf(ang, &sn, &cs);

    size_t base = ((size_t)(b * S_ + s)) * E_ + hh * D_ + i;
    const float* src = isQ ? Q : K;
    float x1 = src[base];
    float x2 = src[base + 32];
    float y1 = x1 * cs - x2 * sn;
    float y2 = x2 * cs + x1 * sn;

    if (isQ) {
        g_Qh[base]      = __float2half_rn(y1 * 0.125f);
        g_Qh[base + 32] = __float2half_rn(y2 * 0.125f);
    } else {
        __half h1 = __float2half_rn(y1);
        __half h2 = __float2half_rn(y2);
        g_Kh[base] = h1;
        g_Kh[base + 32] = h2;
        g_Kl[base] = __float2half_rn(y1 - __half2float(h1));
        g_Kl[base + 32] = __float2half_rn(y2 - __half2float(h2));
    }
}

// ---------------- tensor-core causal flash attention (fp16 2-term) --------
// KV stage: {Kh, Kl, Vh, Vl} tiles of 64 rows x 144B; Q single tile above.
#define AROWB 144
#define KVTILE (64 * AROWB)                 // 9216
#define KVSTAGE (4 * KVTILE)                // 36864
#define Q_OFF (2 * KVSTAGE)                 // 73728
#define ATTN_SMEM (Q_OFF + 128 * AROWB)     // 92160

__device__ __forceinline__ void load_kv(
    uint32_t sb, size_t rowbase, size_t headoff, int k0, int tid) {
#pragma unroll
    for (int p = 0; p < 2; p++) {
        int chunk = tid + p * 256;          // 0..511
        int row = chunk >> 3;               // 0..63
        int c8 = chunk & 7;
        size_t g = (rowbase + k0 + row) * E_ + headoff + c8 * 8;
        uint32_t so = (uint32_t)(row * AROWB + c8 * 16);
        cp16(sb + so,              g_Kh + g);
        cp16(sb + KVTILE + so,     g_Kl + g);
        cp16(sb + 2 * KVTILE + so, g_Vh + g);
        cp16(sb + 3 * KVTILE + so, g_Vl + g);
    }
}

__global__ __launch_bounds__(256, 2)
void flash_attn_tc(__half* __restrict__ Oh) {
    extern __shared__ char smem[];
    const uint32_t sb = smem_u32(smem);
    const int tid = threadIdx.x;
    const int lane = tid & 31;
    const int w = tid >> 5;
    const int qt = gridDim.x - 1 - blockIdx.x;
    const int h = blockIdx.y;
    const int b = blockIdx.z;
    const int q0 = qt * 128;
    const size_t rowbase = (size_t)(b * S_);
    const size_t headoff = (size_t)h * D_;

    // stage Q (single fp16)
#pragma unroll
    for (int p = 0; p < 4; p++) {
        int chunk = tid + p * 256;          // 0..1023
        int row = chunk >> 3;               // 0..127
        int c8 = chunk & 7;
        size_t g = (rowbase + q0 + row) * E_ + headoff + c8 * 8;
        cp16(sb + Q_OFF + (uint32_t)(row * AROWB + c8 * 16), g_Qh + g);
    }
    asm volatile("cp.async.commit_group;" ::: "memory");
    asm volatile("cp.async.wait_group 0;" ::: "memory");
    __syncthreads();

    uint32_t qh[4][4];
    {
        const int arow = w * 16 + (lane & 7) + ((lane >> 3) & 1) * 8;
#pragma unroll
        for (int ks = 0; ks < 4; ks++) {
            const int koff = ks * 16 + (lane >> 4) * 8;
            ldsm4(qh[ks], sb + Q_OFF + (uint32_t)(arow * AROWB + koff * 2));
        }
    }
    __syncthreads();

    float m0 = -INFINITY, m1 = -INFINITY, l0 = 0.f, l1 = 0.f;
    float o[8][4];
#pragma unroll
    for (int t = 0; t < 8; t++)
#pragma unroll
        for (int r = 0; r < 4; r++) o[t][r] = 0.f;

    const int nkb = 2 * (qt + 1);
    load_kv(sb, rowbase, headoff, 0, tid);
    asm volatile("cp.async.commit_group;" ::: "memory");

    for (int kt = 0; kt < nkb; kt++) {
        if (kt + 1 < nkb) {
            load_kv(sb + ((kt + 1) & 1) * KVSTAGE, rowbase, headoff,
                    (kt + 1) * 64, tid);
            asm volatile("cp.async.commit_group;" ::: "memory");
            asm volatile("cp.async.wait_group 1;" ::: "memory");
        } else {
            asm volatile("cp.async.wait_group 0;" ::: "memory");
        }
        __syncthreads();

        const int k0 = kt * 64;
        const bool skip = (q0 + w * 16 + 15) < k0;
        if (!skip) {
            const uint32_t base = sb + (kt & 1) * KVSTAGE;
            float s[8][4];
#pragma unroll
            for (int t = 0; t < 8; t++)
#pragma unroll
                for (int r = 0; r < 4; r++) s[t][r] = 0.f;

            const int nrow = (lane & 7) + ((lane >> 4) & 1) * 8;
#pragma unroll
            for (int ks = 0; ks < 4; ks++) {
                const int koff = ks * 16 + ((lane >> 3) & 1) * 8;
#pragma unroll
                for (int p = 0; p < 4; p++) {
                    uint32_t kh[4], kl[4];
                    uint32_t ao = (uint32_t)((16 * p + nrow) * AROWB + koff * 2);
                    ldsm4(kh, base + ao);
                    ldsm4(kl, base + KVTILE + ao);
                    mma16816(s[2 * p],     qh[ks], &kh[0]);
                    mma16816(s[2 * p],     qh[ks], &kl[0]);
                    mma16816(s[2 * p + 1], qh[ks], &kh[2]);
                    mma16816(s[2 * p + 1], qh[ks], &kl[2]);
                }
            }

            const int row0 = q0 + w * 16 + (lane >> 2);
            if (kt >= 2 * qt) {
#pragma unroll
                for (int t = 0; t < 8; t++) {
                    int col = k0 + t * 8 + (lane & 3) * 2;
                    if (col > row0)         s[t][0] = -1e30f;
                    if (col + 1 > row0)     s[t][1] = -1e30f;
                    if (col > row0 + 8)     s[t][2] = -1e30f;
                    if (col + 1 > row0 + 8) s[t][3] = -1e30f;
                }
            }

            float mx0 = -INFINITY, mx1 = -INFINITY;
#pragma unroll
            for (int t = 0; t < 8; t++) {
                mx0 = fmaxf(mx0, fmaxf(s[t][0], s[t][1]));
                mx1 = fmaxf(mx1, fmaxf(s[t][2], s[t][3]));
            }
#pragma unroll
            for (int off = 1; off <= 2; off <<= 1) {
                mx0 = fmaxf(mx0, __shfl_xor_sync(0xffffffffu, mx0, off));
                mx1 = fmaxf(mx1, __shfl_xor_sync(0xffffffffu, mx1, off));
            }
            float mn0 = fmaxf(m0, mx0), mn1 = fmaxf(m1, mx1);
            float al0 = __expf(m0 - mn0), al1 = __expf(m1 - mn1);
            m0 = mn0; m1 = mn1;
            float rs0 = 0.f, rs1 = 0.f;
#pragma unroll
            for (int t = 0; t < 8; t++) {
                s[t][0] = __expf(s[t][0] - mn0);
                s[t][1] = __expf(s[t][1] - mn0);
                s[t][2] = __expf(s[t][2] - mn1);
                s[t][3] = __expf(s[t][3] - mn1);
                rs0 += s[t][0] + s[t][1];
                rs1 += s[t][2] + s[t][3];
            }
#pragma unroll
            for (int off = 1; off <= 2; off <<= 1) {
                rs0 += __shfl_xor_sync(0xffffffffu, rs0, off);
                rs1 += __shfl_xor_sync(0xffffffffu, rs1, off);
            }
            l0 = l0 * al0 + rs0;
            l1 = l1 * al1 + rs1;
#pragma unroll
            for (int t = 0; t < 8; t++) {
                o[t][0] *= al0; o[t][1] *= al0;
                o[t][2] *= al1; o[t][3] *= al1;
            }

            const int vrow0 = lane & 15;
            const int vcoff = (lane >> 4) * 8;
#pragma unroll
            for (int j = 0; j < 4; j++) {
                uint32_t ph[4];
                ph[0] = pack2h(s[2 * j][0], s[2 * j][1]);
                ph[1] = pack2h(s[2 * j][2], s[2 * j][3]);
                ph[2] = pack2h(s[2 * j + 1][0], s[2 * j + 1][1]);
                ph[3] = pack2h(s[2 * j + 1][2], s[2 * j + 1][3]);
#pragma unroll
                for (int p = 0; p < 4; p++) {
                    uint32_t vh[4], vl[4];
                    uint32_t vo = (uint32_t)((j * 16 + vrow0) * AROWB +
                                             (16 * p + vcoff) * 2);
                    ldsm4t(vh, base + 2 * KVTILE + vo);
                    ldsm4t(vl, base + 3 * KVTILE + vo);
                    mma16816(o[2 * p],     ph, &vh[0]);
                    mma16816(o[2 * p],     ph, &vl[0]);
                    mma16816(o[2 * p + 1], ph, &vh[2]);
                    mma16816(o[2 * p + 1], ph, &vl[2]);
                }
            }
        }
        __syncthreads();
    }

    // epilogue: write attention output as single fp16 (A-side of O-proj)
    const float inv0 = 1.f / l0, inv1 = 1.f / l1;
    const size_t row = rowbase + q0 + w * 16 + (lane >> 2);
    const size_t col = headoff + (lane & 3) * 2;
#pragma unroll
    for (int t = 0; t < 8; t++) {
        *(uint32_t*)&Oh[row * E_ + col + t * 8] =
            pack2h(o[t][0] * inv0, o[t][1] * inv0);
        *(uint32_t*)&Oh[(row + 8) * E_ + col + t * 8] =
            pack2h(o[t][2] * inv1, o[t][3] * inv1);
    }
}

// ---------------------------------------------------------------------------
extern "C" void kernel_launch(void* const* d_in, const int* in_sizes, int n_in,
                              void* d_out, int out_size) {
    const float* q_in = (const float*)d_in[0];
    const float* k_in = (const float*)d_in[1];
    const float* v_in = (const float*)d_in[2];
    const float* Wq = (const float*)d_in[3];
    const float* Wk = (const float*)d_in[4];
    const float* Wv = (const float*)d_in[5];
    const float* Wo = (const float*)d_in[6];
    float* out = (float*)d_out;

    float *Q, *K;
    __half* hA;
    cudaGetSymbolAddress((void**)&Q, g_Q);
    cudaGetSymbolAddress((void**)&K, g_K);
    cudaGetSymbolAddress((void**)&hA, g_hA);

    cudaFuncSetAttribute(gemm_qkv, cudaFuncAttributeMaxDynamicSharedMemorySize,
                         GEMM_SMEM);
    cudaFuncSetAttribute(gemm_o, cudaFuncAttributeMaxDynamicSharedMemorySize,
                         GEMM_SMEM);
    cudaFuncSetAttribute(flash_attn_tc,
                         cudaFuncAttributeMaxDynamicSharedMemorySize, ATTN_SMEM);

    // 0: reset dynamic-tile counters
    zero_ctr<<<1, 32>>>();
    // 1: weight splits (fp16 hi/lo, one launch)
    split_W_all<<<4 * (NW / 8) / 256, 256>>>(Wq, Wk, Wv, Wo);
    // 2: activation converts (fp16 single, one launch)
    conv_A_all<<<3 * (NELEM / 8) / 256, 256>>>(q_in, k_in, v_in);
    // 3: fused persistent Q/K/V projections (1536-tile pool)
    gemm_qkv<<<304, 256, GEMM_SMEM>>>();
    // 4: rope (Q -> single fp16 scaled; K -> fp16 hi/lo)
    int rope_threads = 2 * B_ * S_ * H_ * 32;
    rope_split<<<rope_threads / 256, 256>>>(Q, K);
    // 5: attention -> fp16 output into g_hA
    flash_attn_tc<<<dim3(S_ / 128, H_, B_), 256, ATTN_SMEM>>>(hA);
    // 6: persistent output projection (512-tile pool)
    gemm_o<<<304, 256, GEMM_SMEM>>>(out);
}

// round 11
// speedup vs baseline: 2.4436x; 1.4063x over previous
#include <cuda_runtime.h>
#include <cuda_fp16.h>
#include <math.h>
#include <stdint.h>

#define B_ 4
#define S_ 2048
#define E_ 1024
#define H_ 16
#define D_ 64

static const int MTOT = B_ * S_;          // 8192
#define NELEM (B_ * S_ * E_)              // 8388608
#define NW (E_ * E_)

// ---------------- scratch (__device__ globals; no allocs allowed) ----------
__device__ float g_Q[NELEM];
__device__ float g_K[NELEM];
__device__ __half g_hA[NELEM];    // q-activation staging; later attention output
__device__ __half g_hKs[NELEM];   // k-activation staging
__device__ __half g_hT[NELEM];    // v-activation staging
__device__ __half g_W1[NW];       // Wq (single fp16)
__device__ __half g_W2[NW];       // Wk
__device__ __half g_W3[NW];       // Wv
__device__ __half g_W4[NW];       // Wo
__device__ __half g_Qh[NELEM];                 // roped Q (single, 1/8 folded)
__device__ __half g_Kh[NELEM], g_Kl[NELEM];    // roped K hi/lo
__device__ __half g_Vs[NELEM];                 // V (single fp16)
__device__ unsigned int g_ctr[8];

// ---------------- helpers --------------------------------------------------
__device__ __forceinline__ uint32_t smem_u32(const void* p) {
    uint32_t a;
    asm("{ .reg .u64 t; cvta.to.shared.u64 t, %1; cvt.u32.u64 %0, t; }"
        : "=r"(a) : "l"(p));
    return a;
}
__device__ __forceinline__ void cp16(uint32_t saddr, const void* g) {
    asm volatile("cp.async.cg.shared.global [%0], [%1], 16;"
                 :: "r"(saddr), "l"(g) : "memory");
}
__device__ __forceinline__ void ldsm4(uint32_t* r, uint32_t a) {
    asm volatile("ldmatrix.sync.aligned.m8n8.x4.shared.b16 {%0,%1,%2,%3}, [%4];"
                 : "=r"(r[0]), "=r"(r[1]), "=r"(r[2]), "=r"(r[3]) : "r"(a));
}
__device__ __forceinline__ void ldsm4t(uint32_t* r, uint32_t a) {
    asm volatile("ldmatrix.sync.aligned.m8n8.x4.trans.shared.b16 {%0,%1,%2,%3}, [%4];"
                 : "=r"(r[0]), "=r"(r[1]), "=r"(r[2]), "=r"(r[3]) : "r"(a));
}
__device__ __forceinline__ void mma16816(float* c, const uint32_t* a,
                                         const uint32_t* b) {
    asm volatile(
        "mma.sync.aligned.m16n8k16.row.col.f32.f16.f16.f32 "
        "{%0,%1,%2,%3}, {%4,%5,%6,%7}, {%8,%9}, {%0,%1,%2,%3};"
        : "+f"(c[0]), "+f"(c[1]), "+f"(c[2]), "+f"(c[3])
        : "r"(a[0]), "r"(a[1]), "r"(a[2]), "r"(a[3]), "r"(b[0]), "r"(b[1]));
}
__device__ __forceinline__ uint32_t pack2h(float x0, float x1) {
    __half2 h = __floats2half2_rn(x0, x1);
    return *(uint32_t*)&h;
}

// ---------------- counter reset -------------------------------------------
__global__ void zero_ctr() {
    if (threadIdx.x < 8) g_ctr[threadIdx.x] = 0;
}

// ---------------- weight convert (single fp16), all four in one launch -----
__global__ __launch_bounds__(256)
void conv_W_all(const float* __restrict__ W0, const float* __restrict__ W1,
                const float* __restrict__ W2, const float* __restrict__ W3) {
    int i = blockIdx.x * 256 + threadIdx.x;      // 4 * 2^17
    int which = i >> 17;
    int j = i & 0x1FFFF;
    const float* src = which == 0 ? W0 : which == 1 ? W1 : which == 2 ? W2 : W3;
    __half* dst = which == 0 ? g_W1 : which == 1 ? g_W2
                 : which == 2 ? g_W3 : g_W4;
    float4 v0 = ((const float4*)src)[2 * j];
    float4 v1 = ((const float4*)src)[2 * j + 1];
    float f[8] = {v0.x, v0.y, v0.z, v0.w, v1.x, v1.y, v1.z, v1.w};
    uint32_t h[4];
#pragma unroll
    for (int p = 0; p < 4; p++) h[p] = pack2h(f[2 * p], f[2 * p + 1]);
    ((uint4*)dst)[j] = make_uint4(h[0], h[1], h[2], h[3]);
}

// ---------------- activation convert (single fp16), q/k/v in one launch ----
__global__ __launch_bounds__(256)
void conv_A_all(const float* __restrict__ Aq, const float* __restrict__ Ak,
                const float* __restrict__ Av) {
    int i = blockIdx.x * 256 + threadIdx.x;      // 3 * 2^20
    int which = i >> 20;
    int j = i & 0xFFFFF;
    const float* src = which == 0 ? Aq : which == 1 ? Ak : Av;
    __half* dst = which == 0 ? g_hA : which == 1 ? g_hKs : g_hT;
    float4 v0 = ((const float4*)src)[2 * j];
    float4 v1 = ((const float4*)src)[2 * j + 1];
    float f[8] = {v0.x, v0.y, v0.z, v0.w, v1.x, v1.y, v1.z, v1.w};
    uint32_t h[4];
#pragma unroll
    for (int p = 0; p < 4; p++) h[p] = pack2h(f[2 * p], f[2 * p + 1]);
    ((uint4*)dst)[j] = make_uint4(h[0], h[1], h[2], h[3]);
}

// ---------------- GEMM tile body (128x128, BK=64, 8 warps, 3-stage) -------
// Stage = {A, B} single fp16: 2 tiles x 128 rows x 144B = 36864 B.
#define ROWB 144
#define TILEH (128 * ROWB)                 // 18432
#define STAGEH (2 * TILEH)                 // 36864
#define GEMM_SMEM (3 * STAGEH)             // 110592

__device__ __forceinline__ void load_stage2(
    uint32_t sb, int st, const __half* __restrict__ A,
    const __half* __restrict__ Bs, int bm, int bn, int k0, int tid) {
    uint32_t s0 = sb + st * STAGEH;
#pragma unroll
    for (int p = 0; p < 4; p++) {
        int chunk = tid + p * 256;          // 0..1023
        int row = chunk >> 3;               // 0..127
        int c16 = chunk & 7;
        uint32_t soff = (uint32_t)(row * ROWB + c16 * 16);
        size_t ga = ((size_t)(bm + row) << 10) + k0 + c16 * 8;
        size_t gb = ((size_t)(bn + row) << 10) + k0 + c16 * 8;
        cp16(s0 + soff,         A + ga);
        cp16(s0 + TILEH + soff, Bs + gb);
    }
}

__device__ __forceinline__ void gemm_tile(
    uint32_t sb, int tid, int lane, int wid,
    const __half* __restrict__ A, const __half* __restrict__ Bs,
    float* __restrict__ C, __half* __restrict__ Ch, int bm, int bn) {
    const int wm = wid >> 2;
    const int wn = wid & 3;

    float acc[4][4][4];
#pragma unroll
    for (int i = 0; i < 4; i++)
#pragma unroll
        for (int j = 0; j < 4; j++)
#pragma unroll
            for (int r = 0; r < 4; r++) acc[i][j][r] = 0.f;

    load_stage2(sb, 0, A, Bs, bm, bn, 0, tid);
    asm volatile("cp.async.commit_group;" ::: "memory");
    load_stage2(sb, 1, A, Bs, bm, bn, 64, tid);
    asm volatile("cp.async.commit_group;" ::: "memory");

    const int NCH = E_ / 64;   // 16
    int st = 0;
    for (int c = 0; c < NCH; c++) {
        if (c + 1 < NCH)
            asm volatile("cp.async.wait_group 1;" ::: "memory");
        else
            asm volatile("cp.async.wait_group 0;" ::: "memory");
        __syncthreads();
        if (c + 2 < NCH) {
            int sn = st + 2; if (sn >= 3) sn -= 3;
            load_stage2(sb, sn, A, Bs, bm, bn, (c + 2) * 64, tid);
            asm volatile("cp.async.commit_group;" ::: "memory");
        }

        const uint32_t s0 = sb + st * STAGEH;
        const uint32_t sA = s0, sB = s0 + TILEH;

#pragma unroll
        for (int ks = 0; ks < 64; ks += 16) {
            uint32_t bs[2][4];
            const int brow = wn * 32 + (lane & 7) + ((lane >> 4) & 1) * 8;
            const int bkk = ks + ((lane >> 3) & 1) * 8;
#pragma unroll
            for (int nb = 0; nb < 2; nb++)
                ldsm4(bs[nb], sB + (uint32_t)((brow + nb * 16) * ROWB + bkk * 2));
            const int arow = wm * 64 + (lane & 7) + ((lane >> 3) & 1) * 8;
            const int akk = ks + (lane >> 4) * 8;
#pragma unroll
            for (int mi = 0; mi < 4; mi++) {
                uint32_t a[4];
                ldsm4(a, sA + (uint32_t)((arow + mi * 16) * ROWB + akk * 2));
#pragma unroll
                for (int ni = 0; ni < 4; ni++)
                    mma16816(acc[mi][ni], a, &bs[ni >> 1][(ni & 1) * 2]);
            }
        }
        if (++st == 3) st = 0;
    }
    __syncthreads();   // protect stages vs next tile's prologue loads

    const int r0 = bm + wm * 64 + (lane >> 2);
    const int c0 = bn + wn * 32 + (lane & 3) * 2;
    if (C) {
#pragma unroll
        for (int mi = 0; mi < 4; mi++)
#pragma unroll
            for (int ni = 0; ni < 4; ni++) {
                int row = r0 + mi * 16;
                int col = c0 + ni * 8;
                *(float2*)&C[(size_t)row * E_ + col] =
                    make_float2(acc[mi][ni][0], acc[mi][ni][1]);
                *(float2*)&C[(size_t)(row + 8) * E_ + col] =
                    make_float2(acc[mi][ni][2], acc[mi][ni][3]);
            }
    } else {
#pragma unroll
        for (int mi = 0; mi < 4; mi++)
#pragma unroll
            for (int ni = 0; ni < 4; ni++) {
                int row = r0 + mi * 16;
                int col = c0 + ni * 8;
                *(uint32_t*)&Ch[(size_t)row * E_ + col] =
                    pack2h(acc[mi][ni][0], acc[mi][ni][1]);
                *(uint32_t*)&Ch[(size_t)(row + 8) * E_ + col] =
                    pack2h(acc[mi][ni][2], acc[mi][ni][3]);
            }
    }
}

// Persistent fused Q/K/V projections: 1536 tiles on g_ctr[0].
__global__ __launch_bounds__(256, 2)
void gemm_qkv() {
    extern __shared__ char smem[];
    const uint32_t sb = smem_u32(smem);
    const int tid = threadIdx.x;
    const int lane = tid & 31;
    const int wid = tid >> 5;
    __shared__ unsigned s_t;

    for (;;) {
        if (tid == 0) s_t = atomicAdd(&g_ctr[0], 1u);
        __syncthreads();
        unsigned t = s_t;
        __syncthreads();
        if (t >= 1536u) return;
        int which = t >> 9;
        int rem = t & 511;
        int bm = (rem >> 3) * 128, bn = (rem & 7) * 128;
        if (which == 0)
            gemm_tile(sb, tid, lane, wid, g_hA, g_W1, g_Q, nullptr, bm, bn);
        else if (which == 1)
            gemm_tile(sb, tid, lane, wid, g_hKs, g_W2, g_K, nullptr, bm, bn);
        else
            gemm_tile(sb, tid, lane, wid, g_hT, g_W3, nullptr, g_Vs, bm, bn);
    }
}

// Persistent output projection: 512 tiles on g_ctr[1].
__global__ __launch_bounds__(256, 2)
void gemm_o(float* __restrict__ out) {
    extern __shared__ char smem[];
    const uint32_t sb = smem_u32(smem);
    const int tid = threadIdx.x;
    const int lane = tid & 31;
    const int wid = tid >> 5;
    __shared__ unsigned s_t;

    for (;;) {
        if (tid == 0) s_t = atomicAdd(&g_ctr[1], 1u);
        __syncthreads();
        unsigned t = s_t;
        __syncthreads();
        if (t >= 512u) return;
        int bm = (t >> 3) * 128, bn = (t & 7) * 128;
        gemm_tile(sb, tid, lane, wid, g_hA, g_W4, out, nullptr, bm, bn);
    }
}

// ---------------- RoPE: Q -> single fp16 (1/8 folded), K -> fp16 hi/lo ----
__global__ void rope_split(const float* __restrict__ Q, const float* __restrict__ K) {
    const int per = B_ * S_ * H_ * 32;
    int idx = blockIdx.x * blockDim.x + threadIdx.x;
    if (idx >= 2 * per) return;
    bool isQ = idx < per;
    int r = isQ ? idx : idx - per;
    int i = r & 31;
    int hh = (r >> 5) & (H_ - 1);
    int s = (r >> 9) & (S_ - 1);
    int b = r >> 20;

    float inv_freq = __expf(-(float)i * (logf(10000.0f) / 32.0f));
    float ang = (float)s * inv_freq;
    float sn, cs;
    sincosf(ang, &sn, &cs);

    size_t base = ((size_t)(b * S_ + s)) * E_ + hh * D_ + i;
    const float* src = isQ ? Q : K;
    float x1 = src[base];
    float x2 = src[base + 32];
    float y1 = x1 * cs - x2 * sn;
    float y2 = x2 * cs + x1 * sn;

    if (isQ) {
        g_Qh[base]      = __float2half_rn(y1 * 0.125f);
        g_Qh[base + 32] = __float2half_rn(y2 * 0.125f);
    } else {
        __half h1 = __float2half_rn(y1);
        __half h2 = __float2half_rn(y2);
        g_Kh[base] = h1;
        g_Kh[base + 32] = h2;
        g_Kl[base] = __float2half_rn(y1 - __half2float(h1));
        g_Kl[base + 32] = __float2half_rn(y2 - __half2float(h2));
    }
}

// ---------------- tensor-core causal flash attention ----------------------
// KV stage: {Kh, Kl, Vs} tiles of 64 rows x 144B; Q single tile above.
#define AROWB 144
#define KVTILE (64 * AROWB)                 // 9216
#define KVSTAGE (3 * KVTILE)                // 27648
#define Q_OFF (2 * KVSTAGE)                 // 55296
#define ATTN_SMEM (Q_OFF + 128 * AROWB)     // 73728

__device__ __forceinline__ void load_kv(
    uint32_t sb, size_t rowbase, size_t headoff, int k0, int tid) {
#pragma unroll
    for (int p = 0; p < 2; p++) {
        int chunk = tid + p * 256;          // 0..511
        int row = chunk >> 3;               // 0..63
        int c8 = chunk & 7;
        size_t g = (rowbase + k0 + row) * E_ + headoff + c8 * 8;
        uint32_t so = (uint32_t)(row * AROWB + c8 * 16);
        cp16(sb + so,              g_Kh + g);
        cp16(sb + KVTILE + so,     g_Kl + g);
        cp16(sb + 2 * KVTILE + so, g_Vs + g);
    }
}

__global__ __launch_bounds__(256, 2)
void flash_attn_tc(__half* __restrict__ Oh) {
    extern __shared__ char smem[];
    const uint32_t sb = smem_u32(smem);
    const int tid = threadIdx.x;
    const int lane = tid & 31;
    const int w = tid >> 5;
    const int qt = gridDim.x - 1 - blockIdx.x;
    const int h = blockIdx.y;
    const int b = blockIdx.z;
    const int q0 = qt * 128;
    const size_t rowbase = (size_t)(b * S_);
    const size_t headoff = (size_t)h * D_;

    // stage Q (single fp16)
#pragma unroll
    for (int p = 0; p < 4; p++) {
        int chunk = tid + p * 256;          // 0..1023
        int row = chunk >> 3;               // 0..127
        int c8 = chunk & 7;
        size_t g = (rowbase + q0 + row) * E_ + headoff + c8 * 8;
        cp16(sb + Q_OFF + (uint32_t)(row * AROWB + c8 * 16), g_Qh + g);
    }
    asm volatile("cp.async.commit_group;" ::: "memory");
    asm volatile("cp.async.wait_group 0;" ::: "memory");
    __syncthreads();

    uint32_t qh[4][4];
    {
        const int arow = w * 16 + (lane & 7) + ((lane >> 3) & 1) * 8;
#pragma unroll
        for (int ks = 0; ks < 4; ks++) {
            const int koff = ks * 16 + (lane >> 4) * 8;
            ldsm4(qh[ks], sb + Q_OFF + (uint32_t)(arow * AROWB + koff * 2));
        }
    }
    __syncthreads();

    float m0 = -INFINITY, m1 = -INFINITY, l0 = 0.f, l1 = 0.f;
    float o[8][4];
#pragma unroll
    for (int t = 0; t < 8; t++)
#pragma unroll
        for (int r = 0; r < 4; r++) o[t][r] = 0.f;

    const int nkb = 2 * (qt + 1);
    load_kv(sb, rowbase, headoff, 0, tid);
    asm volatile("cp.async.commit_group;" ::: "memory");

    for (int kt = 0; kt < nkb; kt++) {
        if (kt + 1 < nkb) {
            load_kv(sb + ((kt + 1) & 1) * KVSTAGE, rowbase, headoff,
                    (kt + 1) * 64, tid);
            asm volatile("cp.async.commit_group;" ::: "memory");
            asm volatile("cp.async.wait_group 1;" ::: "memory");
        } else {
            asm volatile("cp.async.wait_group 0;" ::: "memory");
        }
        __syncthreads();

        const int k0 = kt * 64;
        const bool skip = (q0 + w * 16 + 15) < k0;
        if (!skip) {
            const uint32_t base = sb + (kt & 1) * KVSTAGE;
            float s[8][4];
#pragma unroll
            for (int t = 0; t < 8; t++)
#pragma unroll
                for (int r = 0; r < 4; r++) s[t][r] = 0.f;

            const int nrow = (lane & 7) + ((lane >> 4) & 1) * 8;
#pragma unroll
            for (int ks = 0; ks < 4; ks++) {
                const int koff = ks * 16 + ((lane >> 3) & 1) * 8;
#pragma unroll
                for (int p = 0; p < 4; p++) {
                    uint32_t kh[4], kl[4];
                    uint32_t ao = (uint32_t)((16 * p + nrow) * AROWB + koff * 2);
                    ldsm4(kh, base + ao);
                    ldsm4(kl, base + KVTILE + ao);
                    mma16816(s[2 * p],     qh[ks], &kh[0]);
                    mma16816(s[2 * p],     qh[ks], &kl[0]);
                    mma16816(s[2 * p + 1], qh[ks], &kh[2]);
                    mma16816(s[2 * p + 1], qh[ks], &kl[2]);
                }
            }

            const int row0 = q0 + w * 16 + (lane >> 2);
            if (kt >= 2 * qt) {
#pragma unroll
                for (int t = 0; t < 8; t++) {
                    int col = k0 + t * 8 + (lane & 3) * 2;
                    if (col > row0)         s[t][0] = -1e30f;
                    if (col + 1 > row0)     s[t][1] = -1e30f;
                    if (col > row0 + 8)     s[t][2] = -1e30f;
                    if (col + 1 > row0 + 8) s[t][3] = -1e30f;
                }
            }

            float mx0 = -INFINITY, mx1 = -INFINITY;
#pragma unroll
            for (int t = 0; t < 8; t++) {
                mx0 = fmaxf(mx0, fmaxf(s[t][0], s[t][1]));
                mx1 = fmaxf(mx1, fmaxf(s[t][2], s[t][3]));
            }
#pragma unroll
            for (int off = 1; off <= 2; off <<= 1) {
                mx0 = fmaxf(mx0, __shfl_xor_sync(0xffffffffu, mx0, off));
                mx1 = fmaxf(mx1, __shfl_xor_sync(0xffffffffu, mx1, off));
            }
            float mn0 = fmaxf(m0, mx0), mn1 = fmaxf(m1, mx1);
            float al0 = __expf(m0 - mn0), al1 = __expf(m1 - mn1);
            m0 = mn0; m1 = mn1;
            float rs0 = 0.f, rs1 = 0.f;
#pragma unroll
            for (int t = 0; t < 8; t++) {
                s[t][0] = __expf(s[t][0] - mn0);
                s[t][1] = __expf(s[t][1] - mn0);
                s[t][2] = __expf(s[t][2] - mn1);
                s[t][3] = __expf(s[t][3] - mn1);
                rs0 += s[t][0] + s[t][1];
                rs1 += s[t][2] + s[t][3];
            }
#pragma unroll
            for (int off = 1; off <= 2; off <<= 1) {
                rs0 += __shfl_xor_sync(0xffffffffu, rs0, off);
                rs1 += __shfl_xor_sync(0xffffffffu, rs1, off);
            }
            l0 = l0 * al0 + rs0;
            l1 = l1 * al1 + rs1;
#pragma unroll
            for (int t = 0; t < 8; t++) {
                o[t][0] *= al0; o[t][1] *= al0;
                o[t][2] *= al1; o[t][3] *= al1;
            }

            const int vrow0 = lane & 15;
            const int vcoff = (lane >> 4) * 8;
#pragma unroll
            for (int j = 0; j < 4; j++) {
                uint32_t ph[4];
                ph[0] = pack2h(s[2 * j][0], s[2 * j][1]);
                ph[1] = pack2h(s[2 * j][2], s[2 * j][3]);
                ph[2] = pack2h(s[2 * j + 1][0], s[2 * j + 1][1]);
                ph[3] = pack2h(s[2 * j + 1][2], s[2 * j + 1][3]);
#pragma unroll
                for (int p = 0; p < 4; p++) {
                    uint32_t vs[4];
                    uint32_t vo = (uint32_t)((j * 16 + vrow0) * AROWB +
                                             (16 * p + vcoff) * 2);
                    ldsm4t(vs, base + 2 * KVTILE + vo);
                    mma16816(o[2 * p],     ph, &vs[0]);
                    mma16816(o[2 * p + 1], ph, &vs[2]);
                }
            }
        }
        __syncthreads();
    }

    // epilogue: write attention output as single fp16 (A-side of O-proj)
    const float inv0 = 1.f / l0, inv1 = 1.f / l1;
    const size_t row = rowbase + q0 + w * 16 + (lane >> 2);
    const size_t col = headoff + (lane & 3) * 2;
#pragma unroll
    for (int t = 0; t < 8; t++) {
        *(uint32_t*)&Oh[row * E_ + col + t * 8] =
            pack2h(o[t][0] * inv0, o[t][1] * inv0);
        *(uint32_t*)&Oh[(row + 8) * E_ + col + t * 8] =
            pack2h(o[t][2] * inv1, o[t][3] * inv1);
    }
}

// ---------------------------------------------------------------------------
extern "C" void kernel_launch(void* const* d_in, const int* in_sizes, int n_in,
                              void* d_out, int out_size) {
    const float* q_in = (const float*)d_in[0];
    const float* k_in = (const float*)d_in[1];
    const float* v_in = (const float*)d_in[2];
    const float* Wq = (const float*)d_in[3];
    const float* Wk = (const float*)d_in[4];
    const float* Wv = (const float*)d_in[5];
    const float* Wo = (const float*)d_in[6];
    float* out = (float*)d_out;

    float *Q, *K;
    __half* hA;
    cudaGetSymbolAddress((void**)&Q, g_Q);
    cudaGetSymbolAddress((void**)&K, g_K);
    cudaGetSymbolAddress((void**)&hA, g_hA);

    cudaFuncSetAttribute(gemm_qkv, cudaFuncAttributeMaxDynamicSharedMemorySize,
                         GEMM_SMEM);
    cudaFuncSetAttribute(gemm_o, cudaFuncAttributeMaxDynamicSharedMemorySize,
                         GEMM_SMEM);
    cudaFuncSetAttribute(flash_attn_tc,
                         cudaFuncAttributeMaxDynamicSharedMemorySize, ATTN_SMEM);

    // 0: reset dynamic-tile counters
    zero_ctr<<<1, 32>>>();
    // 1: weight converts (single fp16, one launch)
    conv_W_all<<<4 * (NW / 8) / 256, 256>>>(Wq, Wk, Wv, Wo);
    // 2: activation converts (single fp16, one launch)
    conv_A_all<<<3 * (NELEM / 8) / 256, 256>>>(q_in, k_in, v_in);
    // 3: fused persistent Q/K/V projections (1536-tile pool)
    gemm_qkv<<<304, 256, GEMM_SMEM>>>();
    // 4: rope (Q -> single fp16 scaled; K -> fp16 hi/lo)
    int rope_threads = 2 * B_ * S_ * H_ * 32;
    rope_split<<<rope_threads / 256, 256>>>(Q, K);
    // 5: attention -> fp16 output into g_hA   [ncu window]
    flash_attn_tc<<<dim3(S_ / 128, H_, B_), 256, ATTN_SMEM>>>(hA);
    // 6: persistent output projection (512-tile pool)
    gemm_o<<<304, 256, GEMM_SMEM>>>(out);
}

// round 12
// speedup vs baseline: 2.7501x; 1.1254x over previous
#include <cuda_runtime.h>
#include <cuda_fp16.h>
#include <math.h>
#include <stdint.h>

#define B_ 4
#define S_ 2048
#define E_ 1024
#define H_ 16
#define D_ 64

static const int MTOT = B_ * S_;          // 8192
#define NELEM (B_ * S_ * E_)              // 8388608
#define NW (E_ * E_)

// ---------------- scratch (__device__ globals; no allocs allowed) ----------
__device__ float g_Q[NELEM];
__device__ float g_K[NELEM];
__device__ __half g_hA[NELEM];    // q-activation staging; later attention output
__device__ __half g_hKs[NELEM];   // k-activation staging
__device__ __half g_hT[NELEM];    // v-activation staging
__device__ __half g_W1[NW];       // Wq (single fp16)
__device__ __half g_W2[NW];       // Wk
__device__ __half g_W3[NW];       // Wv
__device__ __half g_W4[NW];       // Wo
__device__ __half g_Qh[NELEM];    // roped Q (single, 1/8 folded)
__device__ __half g_Kh[NELEM];    // roped K (single fp16)
__device__ __half g_Vs[NELEM];    // V (single fp16)
__device__ unsigned int g_ctr[8];

// ---------------- helpers --------------------------------------------------
__device__ __forceinline__ uint32_t smem_u32(const void* p) {
    uint32_t a;
    asm("{ .reg .u64 t; cvta.to.shared.u64 t, %1; cvt.u32.u64 %0, t; }"
        : "=r"(a) : "l"(p));
    return a;
}
__device__ __forceinline__ void cp16(uint32_t saddr, const void* g) {
    asm volatile("cp.async.cg.shared.global [%0], [%1], 16;"
                 :: "r"(saddr), "l"(g) : "memory");
}
__device__ __forceinline__ void ldsm4(uint32_t* r, uint32_t a) {
    asm volatile("ldmatrix.sync.aligned.m8n8.x4.shared.b16 {%0,%1,%2,%3}, [%4];"
                 : "=r"(r[0]), "=r"(r[1]), "=r"(r[2]), "=r"(r[3]) : "r"(a));
}
__device__ __forceinline__ void ldsm4t(uint32_t* r, uint32_t a) {
    asm volatile("ldmatrix.sync.aligned.m8n8.x4.trans.shared.b16 {%0,%1,%2,%3}, [%4];"
                 : "=r"(r[0]), "=r"(r[1]), "=r"(r[2]), "=r"(r[3]) : "r"(a));
}
__device__ __forceinline__ void mma16816(float* c, const uint32_t* a,
                                         const uint32_t* b) {
    asm volatile(
        "mma.sync.aligned.m16n8k16.row.col.f32.f16.f16.f32 "
        "{%0,%1,%2,%3}, {%4,%5,%6,%7}, {%8,%9}, {%0,%1,%2,%3};"
        : "+f"(c[0]), "+f"(c[1]), "+f"(c[2]), "+f"(c[3])
        : "r"(a[0]), "r"(a[1]), "r"(a[2]), "r"(a[3]), "r"(b[0]), "r"(b[1]));
}
__device__ __forceinline__ uint32_t pack2h(float x0, float x1) {
    __half2 h = __floats2half2_rn(x0, x1);
    return *(uint32_t*)&h;
}

// ---------------- counter reset -------------------------------------------
__global__ void zero_ctr() {
    if (threadIdx.x < 8) g_ctr[threadIdx.x] = 0;
}

// ---------------- weight convert (single fp16), all four in one launch -----
__global__ __launch_bounds__(256)
void conv_W_all(const float* __restrict__ W0, const float* __restrict__ W1,
                const float* __restrict__ W2, const float* __restrict__ W3) {
    int i = blockIdx.x * 256 + threadIdx.x;      // 4 * 2^17
    int which = i >> 17;
    int j = i & 0x1FFFF;
    const float* src = which == 0 ? W0 : which == 1 ? W1 : which == 2 ? W2 : W3;
    __half* dst = which == 0 ? g_W1 : which == 1 ? g_W2
                 : which == 2 ? g_W3 : g_W4;
    float4 v0 = ((const float4*)src)[2 * j];
    float4 v1 = ((const float4*)src)[2 * j + 1];
    float f[8] = {v0.x, v0.y, v0.z, v0.w, v1.x, v1.y, v1.z, v1.w};
    uint32_t h[4];
#pragma unroll
    for (int p = 0; p < 4; p++) h[p] = pack2h(f[2 * p], f[2 * p + 1]);
    ((uint4*)dst)[j] = make_uint4(h[0], h[1], h[2], h[3]);
}

// ---------------- activation convert (single fp16), q/k/v in one launch ----
__global__ __launch_bounds__(256)
void conv_A_all(const float* __restrict__ Aq, const float* __restrict__ Ak,
                const float* __restrict__ Av) {
    int i = blockIdx.x * 256 + threadIdx.x;      // 3 * 2^20
    int which = i >> 20;
    int j = i & 0xFFFFF;
    const float* src = which == 0 ? Aq : which == 1 ? Ak : Av;
    __half* dst = which == 0 ? g_hA : which == 1 ? g_hKs : g_hT;
    float4 v0 = ((const float4*)src)[2 * j];
    float4 v1 = ((const float4*)src)[2 * j + 1];
    float f[8] = {v0.x, v0.y, v0.z, v0.w, v1.x, v1.y, v1.z, v1.w};
    uint32_t h[4];
#pragma unroll
    for (int p = 0; p < 4; p++) h[p] = pack2h(f[2 * p], f[2 * p + 1]);
    ((uint4*)dst)[j] = make_uint4(h[0], h[1], h[2], h[3]);
}

// ---------------- GEMM tile body (128x128, BK=64, 8 warps, 3-stage) -------
#define ROWB 144
#define TILEH (128 * ROWB)                 // 18432
#define STAGEH (2 * TILEH)                 // 36864
#define GEMM_SMEM (3 * STAGEH)             // 110592

__device__ __forceinline__ void load_stage2(
    uint32_t sb, int st, const __half* __restrict__ A,
    const __half* __restrict__ Bs, int bm, int bn, int k0, int tid) {
    uint32_t s0 = sb + st * STAGEH;
#pragma unroll
    for (int p = 0; p < 4; p++) {
        int chunk = tid + p * 256;          // 0..1023
        int row = chunk >> 3;               // 0..127
        int c16 = chunk & 7;
        uint32_t soff = (uint32_t)(row * ROWB + c16 * 16);
        size_t ga = ((size_t)(bm + row) << 10) + k0 + c16 * 8;
        size_t gb = ((size_t)(bn + row) << 10) + k0 + c16 * 8;
        cp16(s0 + soff,         A + ga);
        cp16(s0 + TILEH + soff, Bs + gb);
    }
}

__device__ __forceinline__ void gemm_tile(
    uint32_t sb, int tid, int lane, int wid,
    const __half* __restrict__ A, const __half* __restrict__ Bs,
    float* __restrict__ C, __half* __restrict__ Ch, int bm, int bn) {
    const int wm = wid >> 2;
    const int wn = wid & 3;

    float acc[4][4][4];
#pragma unroll
    for (int i = 0; i < 4; i++)
#pragma unroll
        for (int j = 0; j < 4; j++)
#pragma unroll
            for (int r = 0; r < 4; r++) acc[i][j][r] = 0.f;

    load_stage2(sb, 0, A, Bs, bm, bn, 0, tid);
    asm volatile("cp.async.commit_group;" ::: "memory");
    load_stage2(sb, 1, A, Bs, bm, bn, 64, tid);
    asm volatile("cp.async.commit_group;" ::: "memory");

    const int NCH = E_ / 64;   // 16
    int st = 0;
    for (int c = 0; c < NCH; c++) {
        if (c + 1 < NCH)
            asm volatile("cp.async.wait_group 1;" ::: "memory");
        else
            asm volatile("cp.async.wait_group 0;" ::: "memory");
        __syncthreads();
        if (c + 2 < NCH) {
            int sn = st + 2; if (sn >= 3) sn -= 3;
            load_stage2(sb, sn, A, Bs, bm, bn, (c + 2) * 64, tid);
            asm volatile("cp.async.commit_group;" ::: "memory");
        }

        const uint32_t s0 = sb + st * STAGEH;
        const uint32_t sA = s0, sB = s0 + TILEH;

#pragma unroll
        for (int ks = 0; ks < 64; ks += 16) {
            uint32_t bs[2][4];
            const int brow = wn * 32 + (lane & 7) + ((lane >> 4) & 1) * 8;
            const int bkk = ks + ((lane >> 3) & 1) * 8;
#pragma unroll
            for (int nb = 0; nb < 2; nb++)
                ldsm4(bs[nb], sB + (uint32_t)((brow + nb * 16) * ROWB + bkk * 2));
            const int arow = wm * 64 + (lane & 7) + ((lane >> 3) & 1) * 8;
            const int akk = ks + (lane >> 4) * 8;
#pragma unroll
            for (int mi = 0; mi < 4; mi++) {
                uint32_t a[4];
                ldsm4(a, sA + (uint32_t)((arow + mi * 16) * ROWB + akk * 2));
#pragma unroll
                for (int ni = 0; ni < 4; ni++)
                    mma16816(acc[mi][ni], a, &bs[ni >> 1][(ni & 1) * 2]);
            }
        }
        if (++st == 3) st = 0;
    }
    __syncthreads();

    const int r0 = bm + wm * 64 + (lane >> 2);
    const int c0 = bn + wn * 32 + (lane & 3) * 2;
    if (C) {
#pragma unroll
        for (int mi = 0; mi < 4; mi++)
#pragma unroll
            for (int ni = 0; ni < 4; ni++) {
                int row = r0 + mi * 16;
                int col = c0 + ni * 8;
                *(float2*)&C[(size_t)row * E_ + col] =
                    make_float2(acc[mi][ni][0], acc[mi][ni][1]);
                *(float2*)&C[(size_t)(row + 8) * E_ + col] =
                    make_float2(acc[mi][ni][2], acc[mi][ni][3]);
            }
    } else {
#pragma unroll
        for (int mi = 0; mi < 4; mi++)
#pragma unroll
            for (int ni = 0; ni < 4; ni++) {
                int row = r0 + mi * 16;
                int col = c0 + ni * 8;
                *(uint32_t*)&Ch[(size_t)row * E_ + col] =
                    pack2h(acc[mi][ni][0], acc[mi][ni][1]);
                *(uint32_t*)&Ch[(size_t)(row + 8) * E_ + col] =
                    pack2h(acc[mi][ni][2], acc[mi][ni][3]);
            }
    }
}

// Persistent fused Q/K/V projections: 1536 tiles on g_ctr[0].
__global__ __launch_bounds__(256, 2)
void gemm_qkv() {
    extern __shared__ char smem[];
    const uint32_t sb = smem_u32(smem);
    const int tid = threadIdx.x;
    const int lane = tid & 31;
    const int wid = tid >> 5;
    __shared__ unsigned s_t;

    for (;;) {
        if (tid == 0) s_t = atomicAdd(&g_ctr[0], 1u);
        __syncthreads();
        unsigned t = s_t;
        __syncthreads();
        if (t >= 1536u) return;
        int which = t >> 9;
        int rem = t & 511;
        int bm = (rem >> 3) * 128, bn = (rem & 7) * 128;
        if (which == 0)
            gemm_tile(sb, tid, lane, wid, g_hA, g_W1, g_Q, nullptr, bm, bn);
        else if (which == 1)
            gemm_tile(sb, tid, lane, wid, g_hKs, g_W2, g_K, nullptr, bm, bn);
        else
            gemm_tile(sb, tid, lane, wid, g_hT, g_W3, nullptr, g_Vs, bm, bn);
    }
}

// Persistent output projection: 512 tiles on g_ctr[1].
__global__ __launch_bounds__(256, 2)
void gemm_o(float* __restrict__ out) {
    extern __shared__ char smem[];
    const uint32_t sb = smem_u32(smem);
    const int tid = threadIdx.x;
    const int lane = tid & 31;
    const int wid = tid >> 5;
    __shared__ unsigned s_t;

    for (;;) {
        if (tid == 0) s_t = atomicAdd(&g_ctr[1], 1u);
        __syncthreads();
        unsigned t = s_t;
        __syncthreads();
        if (t >= 512u) return;
        int bm = (t >> 3) * 128, bn = (t & 7) * 128;
        gemm_tile(sb, tid, lane, wid, g_hA, g_W4, out, nullptr, bm, bn);
    }
}

// ---------------- RoPE: Q,K -> single fp16 (Q gets 1/8 folded) ------------
__global__ void rope_split(const float* __restrict__ Q, const float* __restrict__ K) {
    const int per = B_ * S_ * H_ * 32;
    int idx = blockIdx.x * blockDim.x + threadIdx.x;
    if (idx >= 2 * per) return;
    bool isQ = idx < per;
    int r = isQ ? idx : idx - per;
    int i = r & 31;
    int hh = (r >> 5) & (H_ - 1);
    int s = (r >> 9) & (S_ - 1);
    int b = r >> 20;

    float inv_freq = __expf(-(float)i * (logf(10000.0f) / 32.0f));
    float ang = (float)s * inv_freq;
    float sn, cs;
    sincosf(ang, &sn, &cs);

    size_t base = ((size_t)(b * S_ + s)) * E_ + hh * D_ + i;
    const float* src = isQ ? Q : K;
    float x1 = src[base];
    float x2 = src[base + 32];
    float y1 = x1 * cs - x2 * sn;
    float y2 = x2 * cs + x1 * sn;

    if (isQ) {
        g_Qh[base]      = __float2half_rn(y1 * 0.125f);
        g_Qh[base + 32] = __float2half_rn(y2 * 0.125f);
    } else {
        g_Kh[base]      = __float2half_rn(y1);
        g_Kh[base + 32] = __float2half_rn(y2);
    }
}

// ---------------- tensor-core causal flash attention (all-single fp16) ----
// KV stage: {Ks, Vs} tiles of 64 rows x 144B; 3-stage ring; Q tile above.
#define AROWB 144
#define KVTILE (64 * AROWB)                 // 9216
#define KVSTAGE (2 * KVTILE)                // 18432
#define Q_OFF (3 * KVSTAGE)                 // 55296
#define ATTN_SMEM (Q_OFF + 128 * AROWB)     // 73728

__device__ __forceinline__ void load_kv(
    uint32_t sb, size_t rowbase, size_t headoff, int k0, int tid) {
#pragma unroll
    for (int p = 0; p < 2; p++) {
        int chunk = tid + p * 256;          // 0..511
        int row = chunk >> 3;               // 0..63
        int c8 = chunk & 7;
        size_t g = (rowbase + k0 + row) * E_ + headoff + c8 * 8;
        uint32_t so = (uint32_t)(row * AROWB + c8 * 16);
        cp16(sb + so,          g_Kh + g);
        cp16(sb + KVTILE + so, g_Vs + g);
    }
}

__global__ __launch_bounds__(256, 2)
void flash_attn_tc(__half* __restrict__ Oh) {
    extern __shared__ char smem[];
    const uint32_t sb = smem_u32(smem);
    const int tid = threadIdx.x;
    const int lane = tid & 31;
    const int w = tid >> 5;
    const int qt = gridDim.x - 1 - blockIdx.x;
    const int h = blockIdx.y;
    const int b = blockIdx.z;
    const int q0 = qt * 128;
    const size_t rowbase = (size_t)(b * S_);
    const size_t headoff = (size_t)h * D_;

    // stage Q (single fp16)
#pragma unroll
    for (int p = 0; p < 4; p++) {
        int chunk = tid + p * 256;          // 0..1023
        int row = chunk >> 3;               // 0..127
        int c8 = chunk & 7;
        size_t g = (rowbase + q0 + row) * E_ + headoff + c8 * 8;
        cp16(sb + Q_OFF + (uint32_t)(row * AROWB + c8 * 16), g_Qh + g);
    }
    asm volatile("cp.async.commit_group;" ::: "memory");
    asm volatile("cp.async.wait_group 0;" ::: "memory");
    __syncthreads();

    uint32_t qh[4][4];
    {
        const int arow = w * 16 + (lane & 7) + ((lane >> 3) & 1) * 8;
#pragma unroll
        for (int ks = 0; ks < 4; ks++) {
            const int koff = ks * 16 + (lane >> 4) * 8;
            ldsm4(qh[ks], sb + Q_OFF + (uint32_t)(arow * AROWB + koff * 2));
        }
    }
    __syncthreads();

    float m0 = -INFINITY, m1 = -INFINITY, l0 = 0.f, l1 = 0.f;
    float o[8][4];
#pragma unroll
    for (int t = 0; t < 8; t++)
#pragma unroll
        for (int r = 0; r < 4; r++) o[t][r] = 0.f;

    const int nkb = 2 * (qt + 1);
    // prologue: fill up to 2 stages
    load_kv(sb, rowbase, headoff, 0, tid);
    asm volatile("cp.async.commit_group;" ::: "memory");
    if (1 < nkb) {
        load_kv(sb + KVSTAGE, rowbase, headoff, 64, tid);
        asm volatile("cp.async.commit_group;" ::: "memory");
    }

    int st = 0;
    for (int kt = 0; kt < nkb; kt++) {
        if (kt + 1 < nkb)
            asm volatile("cp.async.wait_group 1;" ::: "memory");
        else
            asm volatile("cp.async.wait_group 0;" ::: "memory");
        __syncthreads();
        if (kt + 2 < nkb) {
            int sn = st + 2; if (sn >= 3) sn -= 3;
            load_kv(sb + sn * KVSTAGE, rowbase, headoff, (kt + 2) * 64, tid);
            asm volatile("cp.async.commit_group;" ::: "memory");
        }

        const int k0 = kt * 64;
        const bool skip = (q0 + w * 16 + 15) < k0;
        if (!skip) {
            const uint32_t base = sb + st * KVSTAGE;
            float s[8][4];
#pragma unroll
            for (int t = 0; t < 8; t++)
#pragma unroll
                for (int r = 0; r < 4; r++) s[t][r] = 0.f;

            const int nrow = (lane & 7) + ((lane >> 4) & 1) * 8;
#pragma unroll
            for (int ks = 0; ks < 4; ks++) {
                const int koff = ks * 16 + ((lane >> 3) & 1) * 8;
#pragma unroll
                for (int p = 0; p < 4; p++) {
                    uint32_t kh[4];
                    ldsm4(kh, base + (uint32_t)((16 * p + nrow) * AROWB + koff * 2));
                    mma16816(s[2 * p],     qh[ks], &kh[0]);
                    mma16816(s[2 * p + 1], qh[ks], &kh[2]);
                }
            }

            const int row0 = q0 + w * 16 + (lane >> 2);
            if (kt >= 2 * qt) {
#pragma unroll
                for (int t = 0; t < 8; t++) {
                    int col = k0 + t * 8 + (lane & 3) * 2;
                    if (col > row0)         s[t][0] = -1e30f;
                    if (col + 1 > row0)     s[t][1] = -1e30f;
                    if (col > row0 + 8)     s[t][2] = -1e30f;
                    if (col + 1 > row0 + 8) s[t][3] = -1e30f;
                }
            }

            float mx0 = -INFINITY, mx1 = -INFINITY;
#pragma unroll
            for (int t = 0; t < 8; t++) {
                mx0 = fmaxf(mx0, fmaxf(s[t][0], s[t][1]));
                mx1 = fmaxf(mx1, fmaxf(s[t][2], s[t][3]));
            }
#pragma unroll
            for (int off = 1; off <= 2; off <<= 1) {
                mx0 = fmaxf(mx0, __shfl_xor_sync(0xffffffffu, mx0, off));
                mx1 = fmaxf(mx1, __shfl_xor_sync(0xffffffffu, mx1, off));
            }
            float mn0 = fmaxf(m0, mx0), mn1 = fmaxf(m1, mx1);
            float al0 = __expf(m0 - mn0), al1 = __expf(m1 - mn1);
            m0 = mn0; m1 = mn1;
            float rs0 = 0.f, rs1 = 0.f;
#pragma unroll
            for (int t = 0; t < 8; t++) {
                s[t][0] = __expf(s[t][0] - mn0);
                s[t][1] = __expf(s[t][1] - mn0);
                s[t][2] = __expf(s[t][2] - mn1);
                s[t][3] = __expf(s[t][3] - mn1);
                rs0 += s[t][0] + s[t][1];
                rs1 += s[t][2] + s[t][3];
            }
#pragma unroll
            for (int off = 1; off <= 2; off <<= 1) {
                rs0 += __shfl_xor_sync(0xffffffffu, rs0, off);
                rs1 += __shfl_xor_sync(0xffffffffu, rs1, off);
            }
            l0 = l0 * al0 + rs0;
            l1 = l1 * al1 + rs1;
#pragma unroll
            for (int t = 0; t < 8; t++) {
                o[t][0] *= al0; o[t][1] *= al0;
                o[t][2] *= al1; o[t][3] *= al1;
            }

            const int vrow0 = lane & 15;
            const int vcoff = (lane >> 4) * 8;
#pragma unroll
            for (int j = 0; j < 4; j++) {
                uint32_t ph[4];
                ph[0] = pack2h(s[2 * j][0], s[2 * j][1]);
                ph[1] = pack2h(s[2 * j][2], s[2 * j][3]);
                ph[2] = pack2h(s[2 * j + 1][0], s[2 * j + 1][1]);
                ph[3] = pack2h(s[2 * j + 1][2], s[2 * j + 1][3]);
#pragma unroll
                for (int p = 0; p < 4; p++) {
                    uint32_t vs[4];
                    uint32_t vo = (uint32_t)((j * 16 + vrow0) * AROWB +
                                             (16 * p + vcoff) * 2);
                    ldsm4t(vs, base + KVTILE + vo);
                    mma16816(o[2 * p],     ph, &vs[0]);
                    mma16816(o[2 * p + 1], ph, &vs[2]);
                }
            }
        }
        __syncthreads();
        if (++st == 3) st = 0;
    }

    // epilogue: write attention output as single fp16 (A-side of O-proj)
    const float inv0 = 1.f / l0, inv1 = 1.f / l1;
    const size_t row = rowbase + q0 + w * 16 + (lane >> 2);
    const size_t col = headoff + (lane & 3) * 2;
#pragma unroll
    for (int t = 0; t < 8; t++) {
        *(uint32_t*)&Oh[row * E_ + col + t * 8] =
            pack2h(o[t][0] * inv0, o[t][1] * inv0);
        *(uint32_t*)&Oh[(row + 8) * E_ + col + t * 8] =
            pack2h(o[t][2] * inv1, o[t][3] * inv1);
    }
}

// ---------------------------------------------------------------------------
extern "C" void kernel_launch(void* const* d_in, const int* in_sizes, int n_in,
                              void* d_out, int out_size) {
    const float* q_in = (const float*)d_in[0];
    const float* k_in = (const float*)d_in[1];
    const float* v_in = (const float*)d_in[2];
    const float* Wq = (const float*)d_in[3];
    const float* Wk = (const float*)d_in[4];
    const float* Wv = (const float*)d_in[5];
    const float* Wo = (const float*)d_in[6];
    float* out = (float*)d_out;

    float *Q, *K;
    __half* hA;
    cudaGetSymbolAddress((void**)&Q, g_Q);
    cudaGetSymbolAddress((void**)&K, g_K);
    cudaGetSymbolAddress((void**)&hA, g_hA);

    cudaFuncSetAttribute(gemm_qkv, cudaFuncAttributeMaxDynamicSharedMemorySize,
                         GEMM_SMEM);
    cudaFuncSetAttribute(gemm_o, cudaFuncAttributeMaxDynamicSharedMemorySize,
                         GEMM_SMEM);
    cudaFuncSetAttribute(flash_attn_tc,
                         cudaFuncAttributeMaxDynamicSharedMemorySize, ATTN_SMEM);

    // 0: reset dynamic-tile counters
    zero_ctr<<<1, 32>>>();
    // 1: weight converts (single fp16, one launch)
    conv_W_all<<<4 * (NW / 8) / 256, 256>>>(Wq, Wk, Wv, Wo);
    // 2: activation converts (single fp16, one launch)
    conv_A_all<<<3 * (NELEM / 8) / 256, 256>>>(q_in, k_in, v_in);
    // 3: fused persistent Q/K/V projections (1536-tile pool)
    gemm_qkv<<<304, 256, GEMM_SMEM>>>();
    // 4: rope (Q, K -> single fp16; Q scaled 1/8)
    int rope_threads = 2 * B_ * S_ * H_ * 32;
    rope_split<<<rope_threads / 256, 256>>>(Q, K);
    // 5: attention -> fp16 output into g_hA   [ncu window]
    flash_attn_tc<<<dim3(S_ / 128, H_, B_), 256, ATTN_SMEM>>>(hA);
    // 6: persistent output projection (512-tile pool)
    gemm_o<<<304, 256, GEMM_SMEM>>>(out);
}